// round 2
// baseline (speedup 1.0000x reference)
#include <cuda_runtime.h>
#include <math_constants.h>

// ---------------------------------------------------------------------------
// Net_6906307412335: 3-layer GAT, N=100000, E=1600000 (+N self loops)
// F: 784 -> 128 -> 256 -> 2, edge-softmax attention, final softmax(axis=1)
// NOTE: edge_index arrives as int32 (JAX x64 disabled downcasts int64).
// ---------------------------------------------------------------------------

#define NN_MAX    100000
#define EE_MAX    1600000
#define ET_MAX    (EE_MAX + NN_MAX)
#define FIN       784
#define D1        128
#define D2        256

// Scratch (device globals: allocation-free rule)
__device__ float g_h   [(size_t)NN_MAX * 256];   // current layer h = z_prev @ W
__device__ float g_agg [(size_t)NN_MAX * 256];   // aggregation / activation buffer
__device__ float g_as  [NN_MAX];
__device__ float g_ad  [NN_MAX];
__device__ float g_m   [NN_MAX];
__device__ float g_sum [NN_MAX];
__device__ float g_h3  [2 * NN_MAX];
__device__ float g_agg3[2 * NN_MAX];

// ---------------------------------------------------------------------------
// SGEMM: C[M,N] = A[M,K] @ B[K,N], row-major, K % 8 == 0, N % 128 == 0
// 128x128 block tile, 8x8 thread tile, BK=8, 256 threads.
// ---------------------------------------------------------------------------
__global__ __launch_bounds__(256) void sgemm128(
    const float* __restrict__ A, const float* __restrict__ B,
    float* __restrict__ C, int M, int N, int K)
{
    __shared__ float As[8][128];
    __shared__ float Bs[8][128];

    const int tid  = threadIdx.x;
    const int row0 = blockIdx.x * 128;
    const int col0 = blockIdx.y * 128;
    const int trow = (tid / 16) * 8;
    const int tcol = (tid % 16) * 8;

    const int aRow = tid >> 1;          // 0..127
    const int aCol = (tid & 1) * 4;     // 0 or 4
    const int bRow = tid >> 5;          // 0..7
    const int bCol = (tid & 31) * 4;    // 0..124

    float acc[8][8];
#pragma unroll
    for (int i = 0; i < 8; i++)
#pragma unroll
        for (int j = 0; j < 8; j++) acc[i][j] = 0.0f;

    const bool aValid = (row0 + aRow) < M;
    const float* Aptr = A + (size_t)(row0 + aRow) * K + aCol;
    const float* Bptr = B + (size_t)bRow * N + col0 + bCol;

    for (int k0 = 0; k0 < K; k0 += 8) {
        float4 av = aValid ? *(const float4*)(Aptr + k0)
                           : make_float4(0.f, 0.f, 0.f, 0.f);
        As[aCol + 0][aRow] = av.x;
        As[aCol + 1][aRow] = av.y;
        As[aCol + 2][aRow] = av.z;
        As[aCol + 3][aRow] = av.w;
        *(float4*)&Bs[bRow][bCol] = *(const float4*)(Bptr + (size_t)k0 * N);
        __syncthreads();

#pragma unroll
        for (int kk = 0; kk < 8; kk++) {
            float ra[8], rb[8];
            *(float4*)&ra[0] = *(const float4*)&As[kk][trow];
            *(float4*)&ra[4] = *(const float4*)&As[kk][trow + 4];
            *(float4*)&rb[0] = *(const float4*)&Bs[kk][tcol];
            *(float4*)&rb[4] = *(const float4*)&Bs[kk][tcol + 4];
#pragma unroll
            for (int i = 0; i < 8; i++)
#pragma unroll
                for (int j = 0; j < 8; j++)
                    acc[i][j] = fmaf(ra[i], rb[j], acc[i][j]);
        }
        __syncthreads();
    }

#pragma unroll
    for (int i = 0; i < 8; i++) {
        int r = row0 + trow + i;
        if (r < M) {
            float* cp = C + (size_t)r * N + col0 + tcol;
            *(float4*)cp       = make_float4(acc[i][0], acc[i][1], acc[i][2], acc[i][3]);
            *(float4*)(cp + 4) = make_float4(acc[i][4], acc[i][5], acc[i][6], acc[i][7]);
        }
    }
}

// ---------------------------------------------------------------------------
// Per-node prep: alpha_src/alpha_dst dots, init m=-inf, s=0, agg row = bias.
// One warp per node.
// ---------------------------------------------------------------------------
__global__ __launch_bounds__(256) void node_prep(
    const float* __restrict__ h, const float* __restrict__ a_s,
    const float* __restrict__ a_d, const float* __restrict__ bias,
    float* __restrict__ as_, float* __restrict__ ad_,
    float* __restrict__ m, float* __restrict__ ssum,
    float* __restrict__ agg, int Nn, int F)
{
    int warp = (blockIdx.x * blockDim.x + threadIdx.x) >> 5;
    int lane = threadIdx.x & 31;
    if (warp >= Nn) return;
    const float* row = h + (size_t)warp * F;
    float s1 = 0.f, s2 = 0.f;
    for (int f = lane; f < F; f += 32) {
        float v = row[f];
        s1 = fmaf(v, a_s[f], s1);
        s2 = fmaf(v, a_d[f], s2);
    }
#pragma unroll
    for (int o = 16; o; o >>= 1) {
        s1 += __shfl_down_sync(0xffffffffu, s1, o);
        s2 += __shfl_down_sync(0xffffffffu, s2, o);
    }
    if (lane == 0) {
        as_[warp]  = s1;
        ad_[warp]  = s2;
        m[warp]    = -CUDART_INF_F;
        ssum[warp] = 0.f;
    }
    float* arow = agg + (size_t)warp * F;
    for (int f = lane; f < F; f += 32) arow[f] = bias[f];
}

// Float atomic max (handles negatives; requires init = -inf)
__device__ __forceinline__ void atomicMaxFloat(float* addr, float value) {
    if (value >= 0.f)
        atomicMax((int*)addr, __float_as_int(value));
    else
        atomicMin((unsigned int*)addr, __float_as_uint(value));
}

__device__ __forceinline__ void edge_nodes(const int* __restrict__ ei,
                                           int i, int E, int& s, int& d) {
    if (i < E) { s = ei[i]; d = ei[(size_t)E + i]; }
    else       { s = d = i - E; }
}

__device__ __forceinline__ float edge_e(const float* as_, const float* ad_,
                                        int s, int d) {
    float x = as_[s] + ad_[d];
    return fmaxf(x, 0.2f * x);   // leaky relu, slope 0.2
}

// Pass A: segment max over dst
__global__ __launch_bounds__(256) void edge_max(
    const int* __restrict__ ei, const float* __restrict__ as_,
    const float* __restrict__ ad_, float* __restrict__ m, int E, int ET)
{
    int i = blockIdx.x * blockDim.x + threadIdx.x;
    if (i >= ET) return;
    int s, d; edge_nodes(ei, i, E, s, d);
    atomicMaxFloat(&m[d], edge_e(as_, ad_, s, d));
}

// Pass B: segment sum of exp(e - m[dst])
__global__ __launch_bounds__(256) void edge_sum(
    const int* __restrict__ ei, const float* __restrict__ as_,
    const float* __restrict__ ad_, const float* __restrict__ m,
    float* __restrict__ ssum, int E, int ET)
{
    int i = blockIdx.x * blockDim.x + threadIdx.x;
    if (i >= ET) return;
    int s, d; edge_nodes(ei, i, E, s, d);
    float e = edge_e(as_, ad_, s, d);
    atomicAdd(&ssum[d], expf(e - m[d]));
}

// Pass C: agg[dst,:] += alpha * h[src,:]   (one warp per edge, float4)
__global__ __launch_bounds__(256) void edge_agg(
    const int* __restrict__ ei, const float* __restrict__ as_,
    const float* __restrict__ ad_, const float* __restrict__ m,
    const float* __restrict__ ssum, const float* __restrict__ h,
    float* __restrict__ agg, int E, int ET, int F)
{
    int warp = (blockIdx.x * blockDim.x + threadIdx.x) >> 5;
    int lane = threadIdx.x & 31;
    if (warp >= ET) return;
    int s, d; edge_nodes(ei, warp, E, s, d);
    float e = edge_e(as_, ad_, s, d);
    float w = expf(e - m[d]) / ssum[d];
    const float4* hs  = (const float4*)(h + (size_t)s * F);
    float*        out = agg + (size_t)d * F;
    for (int f = lane; f * 4 < F; f += 32) {
        float4 v = hs[f];
        atomicAdd(&out[4 * f + 0], w * v.x);
        atomicAdd(&out[4 * f + 1], w * v.y);
        atomicAdd(&out[4 * f + 2], w * v.z);
        atomicAdd(&out[4 * f + 3], w * v.w);
    }
}

__global__ __launch_bounds__(256) void relu_inplace(float* __restrict__ p, size_t n) {
    size_t i = (size_t)blockIdx.x * blockDim.x + threadIdx.x;
    if (i < n) p[i] = fmaxf(p[i], 0.f);
}

// ---------------------------------------------------------------------------
// Layer 3 fused: h3 = z2 @ W3 (K=256, N=2), alpha dots, inits. Warp per node.
// ---------------------------------------------------------------------------
__global__ __launch_bounds__(256) void layer3_prep(
    const float* __restrict__ z2, const float* __restrict__ W3,
    const float* __restrict__ a3s, const float* __restrict__ a3d,
    const float* __restrict__ b3,
    float* __restrict__ h3, float* __restrict__ as_, float* __restrict__ ad_,
    float* __restrict__ m, float* __restrict__ ssum, float* __restrict__ agg,
    int Nn)
{
    int warp = (blockIdx.x * blockDim.x + threadIdx.x) >> 5;
    int lane = threadIdx.x & 31;
    if (warp >= Nn) return;
    const float* row = z2 + (size_t)warp * D2;
    float h0 = 0.f, h1 = 0.f;
    for (int f = lane; f < D2; f += 32) {
        float v = row[f];
        h0 = fmaf(v, W3[2 * f + 0], h0);
        h1 = fmaf(v, W3[2 * f + 1], h1);
    }
#pragma unroll
    for (int o = 16; o; o >>= 1) {
        h0 += __shfl_down_sync(0xffffffffu, h0, o);
        h1 += __shfl_down_sync(0xffffffffu, h1, o);
    }
    if (lane == 0) {
        h3[2 * warp + 0] = h0;
        h3[2 * warp + 1] = h1;
        as_[warp] = h0 * a3s[0] + h1 * a3s[1];
        ad_[warp] = h0 * a3d[0] + h1 * a3d[1];
        m[warp]    = -CUDART_INF_F;
        ssum[warp] = 0.f;
        agg[2 * warp + 0] = b3[0];
        agg[2 * warp + 1] = b3[1];
    }
}

// Pass C for F=2 (thread per edge)
__global__ __launch_bounds__(256) void edge_agg2(
    const int* __restrict__ ei, const float* __restrict__ as_,
    const float* __restrict__ ad_, const float* __restrict__ m,
    const float* __restrict__ ssum, const float* __restrict__ h3,
    float* __restrict__ agg, int E, int ET)
{
    int i = blockIdx.x * blockDim.x + threadIdx.x;
    if (i >= ET) return;
    int s, d; edge_nodes(ei, i, E, s, d);
    float e = edge_e(as_, ad_, s, d);
    float w = expf(e - m[d]) / ssum[d];
    atomicAdd(&agg[2 * d + 0], w * h3[2 * s + 0]);
    atomicAdd(&agg[2 * d + 1], w * h3[2 * s + 1]);
}

// Final: softmax over the 2 logits per node -> d_out
__global__ __launch_bounds__(256) void final_softmax(
    const float* __restrict__ agg, float* __restrict__ out, int Nn)
{
    int i = blockIdx.x * blockDim.x + threadIdx.x;
    if (i >= Nn) return;
    float v0 = agg[2 * i], v1 = agg[2 * i + 1];
    float mm = fmaxf(v0, v1);
    float e0 = expf(v0 - mm), e1 = expf(v1 - mm);
    float inv = 1.f / (e0 + e1);
    out[2 * i]     = e0 * inv;
    out[2 * i + 1] = e1 * inv;
}

// ---------------------------------------------------------------------------
// Launch
// ---------------------------------------------------------------------------
extern "C" void kernel_launch(void* const* d_in, const int* in_sizes, int n_in,
                              void* d_out, int out_size)
{
    const float* x  = (const float*)d_in[0];
    const int*   ei = (const int*)d_in[1];   // int32! (JAX x64 disabled)
    // d_in[2] = batch (unused; gives N)
    const float *W1 = (const float*)d_in[3],  *a1s = (const float*)d_in[4],
                *a1d = (const float*)d_in[5], *b1  = (const float*)d_in[6];
    const float *W2 = (const float*)d_in[7],  *a2s = (const float*)d_in[8],
                *a2d = (const float*)d_in[9], *b2  = (const float*)d_in[10];
    const float *W3 = (const float*)d_in[11], *a3s = (const float*)d_in[12],
                *a3d = (const float*)d_in[13], *b3 = (const float*)d_in[14];

    const int Nn = in_sizes[2];          // nodes (batch length)
    const int E  = in_sizes[1] / 2;      // edges
    const int ET = E + Nn;               // + self loops

    float *h, *agg, *as_, *ad_, *m, *ssum, *h3, *agg3;
    cudaGetSymbolAddress((void**)&h,    g_h);
    cudaGetSymbolAddress((void**)&agg,  g_agg);
    cudaGetSymbolAddress((void**)&as_,  g_as);
    cudaGetSymbolAddress((void**)&ad_,  g_ad);
    cudaGetSymbolAddress((void**)&m,    g_m);
    cudaGetSymbolAddress((void**)&ssum, g_sum);
    cudaGetSymbolAddress((void**)&h3,   g_h3);
    cudaGetSymbolAddress((void**)&agg3, g_agg3);

    const int TB = 256;
    const int nodeWarpBlocks = (Nn * 32 + TB - 1) / TB;
    const int edgeBlocks     = (ET + TB - 1) / TB;
    const int edgeWarpBlocks = (int)(((size_t)ET * 32 + TB - 1) / TB);

    // ---- Layer 1 (Fin=784 -> D1=128) ----
    {
        dim3 grid((Nn + 127) / 128, D1 / 128);
        sgemm128<<<grid, TB>>>(x, W1, h, Nn, D1, FIN);
    }
    node_prep<<<nodeWarpBlocks, TB>>>(h, a1s, a1d, b1, as_, ad_, m, ssum, agg, Nn, D1);
    edge_max<<<edgeBlocks, TB>>>(ei, as_, ad_, m, E, ET);
    edge_sum<<<edgeBlocks, TB>>>(ei, as_, ad_, m, ssum, E, ET);
    edge_agg<<<edgeWarpBlocks, TB>>>(ei, as_, ad_, m, ssum, h, agg, E, ET, D1);
    relu_inplace<<<(int)(((size_t)Nn * D1 + TB - 1) / TB), TB>>>(agg, (size_t)Nn * D1);

    // ---- Layer 2 (D1=128 -> D2=256) ----
    {
        dim3 grid((Nn + 127) / 128, D2 / 128);
        sgemm128<<<grid, TB>>>(agg, W2, h, Nn, D2, D1);
    }
    node_prep<<<nodeWarpBlocks, TB>>>(h, a2s, a2d, b2, as_, ad_, m, ssum, agg, Nn, D2);
    edge_max<<<edgeBlocks, TB>>>(ei, as_, ad_, m, E, ET);
    edge_sum<<<edgeBlocks, TB>>>(ei, as_, ad_, m, ssum, E, ET);
    edge_agg<<<edgeWarpBlocks, TB>>>(ei, as_, ad_, m, ssum, h, agg, E, ET, D2);
    relu_inplace<<<(int)(((size_t)Nn * D2 + TB - 1) / TB), TB>>>(agg, (size_t)Nn * D2);

    // ---- Layer 3 (D2=256 -> 2) + final softmax ----
    layer3_prep<<<nodeWarpBlocks, TB>>>(agg, W3, a3s, a3d, b3,
                                        h3, as_, ad_, m, ssum, agg3, Nn);
    edge_max<<<edgeBlocks, TB>>>(ei, as_, ad_, m, E, ET);
    edge_sum<<<edgeBlocks, TB>>>(ei, as_, ad_, m, ssum, E, ET);
    edge_agg2<<<edgeBlocks, TB>>>(ei, as_, ad_, m, ssum, h3, agg3, E, ET);
    final_softmax<<<(Nn + TB - 1) / TB, TB>>>(agg3, (float*)d_out, Nn);
}

// round 5
// speedup vs baseline: 2.4712x; 2.4712x over previous
#include <cuda_runtime.h>
#include <math_constants.h>

// ---------------------------------------------------------------------------
// Net_6906307412335: 3-layer GAT, N=100000, E=1600000 (+N self loops)
// F: 784 -> 128 -> 256 -> 2, edge-softmax attention, final softmax(axis=1)
// Round 4: fix online-softmax NaN (finite -BIG sentinel instead of -inf;
// -inf - -inf = NaN poisoned empty lanes).
// ---------------------------------------------------------------------------

#define NN_MAX    100000
#define EE_MAX    1600000
#define ET_MAX    (EE_MAX + NN_MAX)
#define FIN       784
#define D1        128
#define D2        256
#define NEG_BIG   (-3.0e38f)

// Scratch (device globals: allocation-free rule)
__device__ float g_h   [(size_t)NN_MAX * 256];
__device__ float g_agg [(size_t)NN_MAX * 256];
__device__ float g_as  [NN_MAX];
__device__ float g_ad  [NN_MAX];
__device__ float g_h3  [2 * NN_MAX];
// CSR scratch
__device__ int   g_cnt   [NN_MAX];
__device__ int   g_excl  [NN_MAX];
__device__ int   g_bsum  [256];
__device__ int   g_rowptr[NN_MAX + 1];
__device__ int   g_cursor[NN_MAX + 1];
__device__ int   g_srcidx[ET_MAX];

// ---------------------------------------------------------------------------
// SGEMM: C[M,N] = A[M,K] @ B[K,N], row-major, K % 8 == 0, N % 128 == 0
// ---------------------------------------------------------------------------
__global__ __launch_bounds__(256) void sgemm128(
    const float* __restrict__ A, const float* __restrict__ B,
    float* __restrict__ C, int M, int N, int K)
{
    __shared__ float As[8][128];
    __shared__ float Bs[8][128];

    const int tid  = threadIdx.x;
    const int row0 = blockIdx.x * 128;
    const int col0 = blockIdx.y * 128;
    const int trow = (tid / 16) * 8;
    const int tcol = (tid % 16) * 8;

    const int aRow = tid >> 1;
    const int aCol = (tid & 1) * 4;
    const int bRow = tid >> 5;
    const int bCol = (tid & 31) * 4;

    float acc[8][8];
#pragma unroll
    for (int i = 0; i < 8; i++)
#pragma unroll
        for (int j = 0; j < 8; j++) acc[i][j] = 0.0f;

    const bool aValid = (row0 + aRow) < M;
    const float* Aptr = A + (size_t)(row0 + aRow) * K + aCol;
    const float* Bptr = B + (size_t)bRow * N + col0 + bCol;

    for (int k0 = 0; k0 < K; k0 += 8) {
        float4 av = aValid ? *(const float4*)(Aptr + k0)
                           : make_float4(0.f, 0.f, 0.f, 0.f);
        As[aCol + 0][aRow] = av.x;
        As[aCol + 1][aRow] = av.y;
        As[aCol + 2][aRow] = av.z;
        As[aCol + 3][aRow] = av.w;
        *(float4*)&Bs[bRow][bCol] = *(const float4*)(Bptr + (size_t)k0 * N);
        __syncthreads();

#pragma unroll
        for (int kk = 0; kk < 8; kk++) {
            float ra[8], rb[8];
            *(float4*)&ra[0] = *(const float4*)&As[kk][trow];
            *(float4*)&ra[4] = *(const float4*)&As[kk][trow + 4];
            *(float4*)&rb[0] = *(const float4*)&Bs[kk][tcol];
            *(float4*)&rb[4] = *(const float4*)&Bs[kk][tcol + 4];
#pragma unroll
            for (int i = 0; i < 8; i++)
#pragma unroll
                for (int j = 0; j < 8; j++)
                    acc[i][j] = fmaf(ra[i], rb[j], acc[i][j]);
        }
        __syncthreads();
    }

#pragma unroll
    for (int i = 0; i < 8; i++) {
        int r = row0 + trow + i;
        if (r < M) {
            float* cp = C + (size_t)r * N + col0 + tcol;
            *(float4*)cp       = make_float4(acc[i][0], acc[i][1], acc[i][2], acc[i][3]);
            *(float4*)(cp + 4) = make_float4(acc[i][4], acc[i][5], acc[i][6], acc[i][7]);
        }
    }
}

// ---------------------------------------------------------------------------
// CSR construction (counting sort by dst)
// ---------------------------------------------------------------------------
__global__ __launch_bounds__(256) void zero_counts(int* __restrict__ cnt, int Nn) {
    int i = blockIdx.x * blockDim.x + threadIdx.x;
    if (i < Nn) cnt[i] = 0;
}

__global__ __launch_bounds__(256) void hist_dst(
    const int* __restrict__ ei, int* __restrict__ cnt, int E, int ET)
{
    int i = blockIdx.x * blockDim.x + threadIdx.x;
    if (i >= ET) return;
    int d = (i < E) ? ei[(size_t)E + i] : i - E;
    atomicAdd(&cnt[d], 1);
}

// 1024-wide inclusive Hillis-Steele -> exclusive per-chunk + block sums
__global__ __launch_bounds__(1024) void scan1024(
    const int* __restrict__ cnt, int n, int* __restrict__ excl, int* __restrict__ bsum)
{
    __shared__ int sm[1024];
    int t = threadIdx.x;
    int gid = blockIdx.x * 1024 + t;
    int v = (gid < n) ? cnt[gid] : 0;
    sm[t] = v;
    __syncthreads();
#pragma unroll
    for (int off = 1; off < 1024; off <<= 1) {
        int u = (t >= off) ? sm[t - off] : 0;
        __syncthreads();
        sm[t] += u;
        __syncthreads();
    }
    if (gid < n) excl[gid] = sm[t] - v;
    if (t == 1023) bsum[blockIdx.x] = sm[1023];
}

__global__ void scan_bsum(int* __restrict__ bsum, int nb) {
    if (threadIdx.x == 0 && blockIdx.x == 0) {
        int acc = 0;
        for (int i = 0; i < nb; i++) { int t = bsum[i]; bsum[i] = acc; acc += t; }
    }
}

__global__ __launch_bounds__(256) void add_offsets(
    const int* __restrict__ excl, const int* __restrict__ bsum,
    int* __restrict__ rowptr, int* __restrict__ cursor, int Nn, int ET)
{
    int i = blockIdx.x * blockDim.x + threadIdx.x;
    if (i < Nn) {
        int v = excl[i] + bsum[i >> 10];
        rowptr[i] = v;
        cursor[i] = v;
    } else if (i == Nn) {
        rowptr[Nn] = ET;
    }
}

__global__ __launch_bounds__(256) void scatter_edges(
    const int* __restrict__ ei, int* __restrict__ cursor,
    int* __restrict__ srcidx, int E, int ET)
{
    int i = blockIdx.x * blockDim.x + threadIdx.x;
    if (i >= ET) return;
    int s, d;
    if (i < E) { s = ei[i]; d = ei[(size_t)E + i]; }
    else       { s = d = i - E; }
    int pos = atomicAdd(&cursor[d], 1);
    srcidx[pos] = s;
}

// ---------------------------------------------------------------------------
// Per-node alpha dots (one warp per node)
// ---------------------------------------------------------------------------
__global__ __launch_bounds__(256) void node_prep(
    const float* __restrict__ h, const float* __restrict__ a_s,
    const float* __restrict__ a_d,
    float* __restrict__ as_, float* __restrict__ ad_, int Nn, int F)
{
    int warp = (blockIdx.x * blockDim.x + threadIdx.x) >> 5;
    int lane = threadIdx.x & 31;
    if (warp >= Nn) return;
    const float* row = h + (size_t)warp * F;
    float s1 = 0.f, s2 = 0.f;
    for (int f = lane; f < F; f += 32) {
        float v = row[f];
        s1 = fmaf(v, a_s[f], s1);
        s2 = fmaf(v, a_d[f], s2);
    }
#pragma unroll
    for (int o = 16; o; o >>= 1) {
        s1 += __shfl_down_sync(0xffffffffu, s1, o);
        s2 += __shfl_down_sync(0xffffffffu, s2, o);
    }
    if (lane == 0) { as_[warp] = s1; ad_[warp] = s2; }
}

// ---------------------------------------------------------------------------
// Fused GAT aggregation over CSR: online softmax + weighted gather + bias(+relu)
// One warp per dst node. F in {128, 256}; lanes own F/32 features.
// m is initialized to a finite -BIG (NOT -inf): empty lanes must combine as
// exp(m - m) = exp(0) with zero s, never -inf - -inf = NaN.
// ---------------------------------------------------------------------------
template<int F, bool RELU>
__global__ __launch_bounds__(256) void gat_agg_csr(
    const int* __restrict__ rowptr, const int* __restrict__ srcidx,
    const float* __restrict__ as_, const float* __restrict__ ad_,
    const float* __restrict__ h, const float* __restrict__ bias,
    float* __restrict__ out, int Nn)
{
    constexpr int NV = F / 128;   // float4s per lane
    int warp = (blockIdx.x * blockDim.x + threadIdx.x) >> 5;
    int lane = threadIdx.x & 31;
    if (warp >= Nn) return;

    const int beg = rowptr[warp];
    const int end = rowptr[warp + 1];
    const float adv = ad_[warp];

    // Phase 1: online softmax stats (edges strided across lanes)
    float m = NEG_BIG, s = 0.f;
    for (int i = beg + lane; i < end; i += 32) {
        float x = as_[srcidx[i]] + adv;
        x = fmaxf(x, 0.2f * x);
        float mn = fmaxf(m, x);
        s = s * __expf(m - mn) + __expf(x - mn);
        m = mn;
    }
#pragma unroll
    for (int o = 16; o; o >>= 1) {
        float mo = __shfl_xor_sync(0xffffffffu, m, o);
        float so = __shfl_xor_sync(0xffffffffu, s, o);
        float mn = fmaxf(m, mo);
        s = s * __expf(m - mn) + so * __expf(mo - mn);
        m = mn;
    }
    const float inv = 1.f / s;   // every node has a self loop -> s > 0

    // Phase 2: weighted feature gather (lanes own features, loop over edges)
    float4 acc[NV];
#pragma unroll
    for (int j = 0; j < NV; j++) acc[j] = make_float4(0.f, 0.f, 0.f, 0.f);

    for (int i = beg; i < end; i++) {
        int src = srcidx[i];                       // uniform across warp
        float x = as_[src] + adv;
        x = fmaxf(x, 0.2f * x);
        float w = __expf(x - m);
        const float4* hp = (const float4*)(h + (size_t)src * F);
#pragma unroll
        for (int j = 0; j < NV; j++) {
            float4 v = hp[lane + 32 * j];
            acc[j].x = fmaf(w, v.x, acc[j].x);
            acc[j].y = fmaf(w, v.y, acc[j].y);
            acc[j].z = fmaf(w, v.z, acc[j].z);
            acc[j].w = fmaf(w, v.w, acc[j].w);
        }
    }

    float4* op = (float4*)(out + (size_t)warp * F);
    const float4* bp = (const float4*)bias;
#pragma unroll
    for (int j = 0; j < NV; j++) {
        float4 b = bp[lane + 32 * j];
        float4 r;
        r.x = fmaf(acc[j].x, inv, b.x);
        r.y = fmaf(acc[j].y, inv, b.y);
        r.z = fmaf(acc[j].z, inv, b.z);
        r.w = fmaf(acc[j].w, inv, b.w);
        if (RELU) {
            r.x = fmaxf(r.x, 0.f); r.y = fmaxf(r.y, 0.f);
            r.z = fmaxf(r.z, 0.f); r.w = fmaxf(r.w, 0.f);
        }
        op[lane + 32 * j] = r;
    }
}

// ---------------------------------------------------------------------------
// Layer 3: h3 = z2 @ W3 (K=256, N=2) + alpha dots. One warp per node.
// ---------------------------------------------------------------------------
__global__ __launch_bounds__(256) void layer3_prep(
    const float* __restrict__ z2, const float* __restrict__ W3,
    const float* __restrict__ a3s, const float* __restrict__ a3d,
    float* __restrict__ h3, float* __restrict__ as_, float* __restrict__ ad_,
    int Nn)
{
    int warp = (blockIdx.x * blockDim.x + threadIdx.x) >> 5;
    int lane = threadIdx.x & 31;
    if (warp >= Nn) return;
    const float* row = z2 + (size_t)warp * D2;
    float h0 = 0.f, h1 = 0.f;
    for (int f = lane; f < D2; f += 32) {
        float v = row[f];
        h0 = fmaf(v, W3[2 * f + 0], h0);
        h1 = fmaf(v, W3[2 * f + 1], h1);
    }
#pragma unroll
    for (int o = 16; o; o >>= 1) {
        h0 += __shfl_down_sync(0xffffffffu, h0, o);
        h1 += __shfl_down_sync(0xffffffffu, h1, o);
    }
    if (lane == 0) {
        h3[2 * warp + 0] = h0;
        h3[2 * warp + 1] = h1;
        as_[warp] = h0 * a3s[0] + h1 * a3s[1];
        ad_[warp] = h0 * a3d[0] + h1 * a3d[1];
    }
}

// ---------------------------------------------------------------------------
// Layer 3 aggregate (F=2) + bias + final softmax, fused. One warp per node.
// ---------------------------------------------------------------------------
__global__ __launch_bounds__(256) void gat_layer3_out(
    const int* __restrict__ rowptr, const int* __restrict__ srcidx,
    const float* __restrict__ as_, const float* __restrict__ ad_,
    const float* __restrict__ h3, const float* __restrict__ b3,
    float* __restrict__ out, int Nn)
{
    int warp = (blockIdx.x * blockDim.x + threadIdx.x) >> 5;
    int lane = threadIdx.x & 31;
    if (warp >= Nn) return;

    const int beg = rowptr[warp];
    const int end = rowptr[warp + 1];
    const float adv = ad_[warp];

    float m = NEG_BIG, s = 0.f;
    float a0 = 0.f, a1 = 0.f;
    for (int i = beg + lane; i < end; i += 32) {
        int src = srcidx[i];
        float x = as_[src] + adv;
        x = fmaxf(x, 0.2f * x);
        float mn = fmaxf(m, x);
        float sc = __expf(m - mn);
        float w  = __expf(x - mn);
        s  = s * sc + w;
        a0 = a0 * sc + w * h3[2 * src + 0];
        a1 = a1 * sc + w * h3[2 * src + 1];
        m = mn;
    }
#pragma unroll
    for (int o = 16; o; o >>= 1) {
        float mo  = __shfl_xor_sync(0xffffffffu, m, o);
        float so  = __shfl_xor_sync(0xffffffffu, s, o);
        float a0o = __shfl_xor_sync(0xffffffffu, a0, o);
        float a1o = __shfl_xor_sync(0xffffffffu, a1, o);
        float mn = fmaxf(m, mo);
        float c0 = __expf(m - mn), c1 = __expf(mo - mn);
        s  = s * c0 + so * c1;
        a0 = a0 * c0 + a0o * c1;
        a1 = a1 * c0 + a1o * c1;
        m = mn;
    }
    if (lane == 0) {
        float inv = 1.f / s;
        float v0 = a0 * inv + b3[0];
        float v1 = a1 * inv + b3[1];
        float mm = fmaxf(v0, v1);
        float e0 = __expf(v0 - mm), e1 = __expf(v1 - mm);
        float d = 1.f / (e0 + e1);
        out[2 * warp + 0] = e0 * d;
        out[2 * warp + 1] = e1 * d;
    }
}

// ---------------------------------------------------------------------------
// Launch
// ---------------------------------------------------------------------------
extern "C" void kernel_launch(void* const* d_in, const int* in_sizes, int n_in,
                              void* d_out, int out_size)
{
    const float* x  = (const float*)d_in[0];
    const int*   ei = (const int*)d_in[1];   // int32 (JAX x64 disabled)
    const float *W1 = (const float*)d_in[3],  *a1s = (const float*)d_in[4],
                *a1d = (const float*)d_in[5], *b1  = (const float*)d_in[6];
    const float *W2 = (const float*)d_in[7],  *a2s = (const float*)d_in[8],
                *a2d = (const float*)d_in[9], *b2  = (const float*)d_in[10];
    const float *W3 = (const float*)d_in[11], *a3s = (const float*)d_in[12],
                *a3d = (const float*)d_in[13], *b3 = (const float*)d_in[14];

    const int Nn = in_sizes[2];
    const int E  = in_sizes[1] / 2;
    const int ET = E + Nn;

    float *h, *agg, *as_, *ad_, *h3;
    int *cnt, *excl, *bsum, *rowptr, *cursor, *srcidx;
    cudaGetSymbolAddress((void**)&h,      g_h);
    cudaGetSymbolAddress((void**)&agg,    g_agg);
    cudaGetSymbolAddress((void**)&as_,    g_as);
    cudaGetSymbolAddress((void**)&ad_,    g_ad);
    cudaGetSymbolAddress((void**)&h3,     g_h3);
    cudaGetSymbolAddress((void**)&cnt,    g_cnt);
    cudaGetSymbolAddress((void**)&excl,   g_excl);
    cudaGetSymbolAddress((void**)&bsum,   g_bsum);
    cudaGetSymbolAddress((void**)&rowptr, g_rowptr);
    cudaGetSymbolAddress((void**)&cursor, g_cursor);
    cudaGetSymbolAddress((void**)&srcidx, g_srcidx);

    const int TB = 256;
    const int nodeWarpBlocks = (int)(((size_t)Nn * 32 + TB - 1) / TB);
    const int edgeBlocks     = (ET + TB - 1) / TB;
    const int nodeBlocks     = (Nn + TB) / TB;      // covers Nn+1 for add_offsets
    const int scanBlocks     = (Nn + 1023) / 1024;

    // ---- CSR build (once; shared by all 3 layers) ----
    zero_counts<<<(Nn + TB - 1) / TB, TB>>>(cnt, Nn);
    hist_dst<<<edgeBlocks, TB>>>(ei, cnt, E, ET);
    scan1024<<<scanBlocks, 1024>>>(cnt, Nn, excl, bsum);
    scan_bsum<<<1, 32>>>(bsum, scanBlocks);
    add_offsets<<<nodeBlocks, TB>>>(excl, bsum, rowptr, cursor, Nn, ET);
    scatter_edges<<<edgeBlocks, TB>>>(ei, cursor, srcidx, E, ET);

    // ---- Layer 1 (784 -> 128) ----
    {
        dim3 grid((Nn + 127) / 128, D1 / 128);
        sgemm128<<<grid, TB>>>(x, W1, h, Nn, D1, FIN);
    }
    node_prep<<<nodeWarpBlocks, TB>>>(h, a1s, a1d, as_, ad_, Nn, D1);
    gat_agg_csr<D1, true><<<nodeWarpBlocks, TB>>>(rowptr, srcidx, as_, ad_, h, b1, agg, Nn);

    // ---- Layer 2 (128 -> 256) ----
    {
        dim3 grid((Nn + 127) / 128, D2 / 128);
        sgemm128<<<grid, TB>>>(agg, W2, h, Nn, D2, D1);
    }
    node_prep<<<nodeWarpBlocks, TB>>>(h, a2s, a2d, as_, ad_, Nn, D2);
    gat_agg_csr<D2, true><<<nodeWarpBlocks, TB>>>(rowptr, srcidx, as_, ad_, h, b2, agg, Nn);

    // ---- Layer 3 (256 -> 2) + final softmax ----
    layer3_prep<<<nodeWarpBlocks, TB>>>(agg, W3, a3s, a3d, h3, as_, ad_, Nn);
    gat_layer3_out<<<nodeWarpBlocks, TB>>>(rowptr, srcidx, as_, ad_, h3, b3,
                                           (float*)d_out, Nn);
}

// round 7
// speedup vs baseline: 2.9411x; 1.1902x over previous
#include <cuda_runtime.h>
#include <math_constants.h>
#include <cstdint>

// ---------------------------------------------------------------------------
// Net_6906307412335: 3-layer GAT, N=100000, E=1600000 (+N self loops)
// F: 784 -> 128 -> 256 -> 2, edge-softmax attention, final softmax(axis=1)
// Round 5: GEMMs on tensor cores (mma.sync tf32, 3-term tf32x2 split for
// fp32-level accuracy). Everything else unchanged from the passing round-4.
// ---------------------------------------------------------------------------

#define NN_MAX    100000
#define EE_MAX    1600000
#define ET_MAX    (EE_MAX + NN_MAX)
#define FIN       784
#define D1        128
#define D2        256
#define NEG_BIG   (-3.0e38f)

// Scratch (device globals: allocation-free rule)
__device__ float g_h   [(size_t)NN_MAX * 256];
__device__ float g_agg [(size_t)NN_MAX * 256];
__device__ float g_as  [NN_MAX];
__device__ float g_ad  [NN_MAX];
__device__ float g_h3  [2 * NN_MAX];
// CSR scratch
__device__ int   g_cnt   [NN_MAX];
__device__ int   g_excl  [NN_MAX];
__device__ int   g_bsum  [256];
__device__ int   g_rowptr[NN_MAX + 1];
__device__ int   g_cursor[NN_MAX + 1];
__device__ int   g_srcidx[ET_MAX];

// ---------------------------------------------------------------------------
// tf32x2 split: v ~= hi + lo, both exactly tf32-representable.
// ---------------------------------------------------------------------------
__device__ __forceinline__ void split_tf32(float v, uint32_t& hi, uint32_t& lo) {
    asm("cvt.rna.tf32.f32 %0, %1;" : "=r"(hi) : "f"(v));
    float h = __uint_as_float(hi);
    asm("cvt.rna.tf32.f32 %0, %1;" : "=r"(lo) : "f"(v - h));
}

__device__ __forceinline__ void mma_tf32(float* c, const uint32_t* a, const uint32_t* b) {
    asm volatile(
        "mma.sync.aligned.m16n8k8.row.col.f32.tf32.tf32.f32 "
        "{%0,%1,%2,%3}, {%4,%5,%6,%7}, {%8,%9}, {%0,%1,%2,%3};"
        : "+f"(c[0]), "+f"(c[1]), "+f"(c[2]), "+f"(c[3])
        : "r"(a[0]), "r"(a[1]), "r"(a[2]), "r"(a[3]), "r"(b[0]), "r"(b[1]));
}

// ---------------------------------------------------------------------------
// Tensor-core GEMM: C[M,N] = A[M,K] @ B[K,N], row-major.
// K % 16 == 0, N % 128 == 0. Block 128x128xBK16, 256 thr, warp tile 64x32.
// 3 mma passes per tile: hi*hi + hi*lo + lo*hi (~fp32 accuracy).
// ---------------------------------------------------------------------------
__global__ __launch_bounds__(256) void gemm_tf32x2(
    const float* __restrict__ A, const float* __restrict__ B,
    float* __restrict__ C, int M, int N, int K)
{
    __shared__ uint32_t AsH[128][17], AsL[128][17];   // [m][k], pad 1
    __shared__ uint32_t BsH[16][132], BsL[16][132];   // [k][n], pad 4

    const int tid  = threadIdx.x;
    const int row0 = blockIdx.x * 128;
    const int col0 = blockIdx.y * 128;
    const int lane = tid & 31;
    const int wid  = tid >> 5;
    const int wm   = (wid >> 2) * 64;   // 0 / 64
    const int wn   = (wid & 3) * 32;    // 0 / 32 / 64 / 96
    const int g    = lane >> 2;         // 0..7
    const int t4   = lane & 3;          // 0..3

    float acc[4][4][4];
#pragma unroll
    for (int mt = 0; mt < 4; mt++)
#pragma unroll
        for (int nt = 0; nt < 4; nt++)
#pragma unroll
            for (int r = 0; r < 4; r++) acc[mt][nt][r] = 0.f;

    for (int k0 = 0; k0 < K; k0 += 16) {
        // ---- stage A tile (128x16) ----
#pragma unroll
        for (int r = 0; r < 2; r++) {
            int idx = tid + 256 * r;          // 0..511
            int ar  = idx >> 2;               // 0..127
            int ak  = (idx & 3) * 4;          // 0,4,8,12
            float4 v = (row0 + ar < M)
                ? *(const float4*)(A + (size_t)(row0 + ar) * K + k0 + ak)
                : make_float4(0.f, 0.f, 0.f, 0.f);
            uint32_t h0,l0,h1,l1,h2,l2,h3,l3;
            split_tf32(v.x, h0, l0); split_tf32(v.y, h1, l1);
            split_tf32(v.z, h2, l2); split_tf32(v.w, h3, l3);
            AsH[ar][ak+0]=h0; AsH[ar][ak+1]=h1; AsH[ar][ak+2]=h2; AsH[ar][ak+3]=h3;
            AsL[ar][ak+0]=l0; AsL[ar][ak+1]=l1; AsL[ar][ak+2]=l2; AsL[ar][ak+3]=l3;
        }
        // ---- stage B tile (16x128) ----
#pragma unroll
        for (int r = 0; r < 2; r++) {
            int idx = tid + 256 * r;
            int bk  = idx >> 5;               // 0..15
            int bn  = (idx & 31) * 4;         // 0..124
            float4 v = *(const float4*)(B + (size_t)(k0 + bk) * N + col0 + bn);
            uint32_t h0,l0,h1,l1,h2,l2,h3,l3;
            split_tf32(v.x, h0, l0); split_tf32(v.y, h1, l1);
            split_tf32(v.z, h2, l2); split_tf32(v.w, h3, l3);
            BsH[bk][bn+0]=h0; BsH[bk][bn+1]=h1; BsH[bk][bn+2]=h2; BsH[bk][bn+3]=h3;
            BsL[bk][bn+0]=l0; BsL[bk][bn+1]=l1; BsL[bk][bn+2]=l2; BsL[bk][bn+3]=l3;
        }
        __syncthreads();

#pragma unroll
        for (int ks = 0; ks < 2; ks++) {
            const int kb = ks * 8;
            uint32_t bh[4][2], bl[4][2];
#pragma unroll
            for (int nt = 0; nt < 4; nt++) {
                int n = wn + nt * 8 + g;
                bh[nt][0] = BsH[kb + t4][n];     bh[nt][1] = BsH[kb + t4 + 4][n];
                bl[nt][0] = BsL[kb + t4][n];     bl[nt][1] = BsL[kb + t4 + 4][n];
            }
#pragma unroll
            for (int mt = 0; mt < 4; mt++) {
                int mr = wm + mt * 16 + g;
                uint32_t ah[4], al[4];
                ah[0] = AsH[mr][kb+t4];   ah[1] = AsH[mr+8][kb+t4];
                ah[2] = AsH[mr][kb+t4+4]; ah[3] = AsH[mr+8][kb+t4+4];
                al[0] = AsL[mr][kb+t4];   al[1] = AsL[mr+8][kb+t4];
                al[2] = AsL[mr][kb+t4+4]; al[3] = AsL[mr+8][kb+t4+4];
#pragma unroll
                for (int nt = 0; nt < 4; nt++) {
                    mma_tf32(acc[mt][nt], ah, bh[nt]);   // hi*hi
                    mma_tf32(acc[mt][nt], ah, bl[nt]);   // hi*lo
                    mma_tf32(acc[mt][nt], al, bh[nt]);   // lo*hi
                }
            }
        }
        __syncthreads();
    }

    // ---- epilogue ----
#pragma unroll
    for (int mt = 0; mt < 4; mt++) {
#pragma unroll
        for (int nt = 0; nt < 4; nt++) {
            int r = row0 + wm + mt * 16 + g;
            int c = col0 + wn + nt * 8 + 2 * t4;
            if (r < M)
                *(float2*)(C + (size_t)r * N + c) =
                    make_float2(acc[mt][nt][0], acc[mt][nt][1]);
            if (r + 8 < M)
                *(float2*)(C + (size_t)(r + 8) * N + c) =
                    make_float2(acc[mt][nt][2], acc[mt][nt][3]);
        }
    }
}

// ---------------------------------------------------------------------------
// CSR construction (counting sort by dst)
// ---------------------------------------------------------------------------
__global__ __launch_bounds__(256) void zero_counts(int* __restrict__ cnt, int Nn) {
    int i = blockIdx.x * blockDim.x + threadIdx.x;
    if (i < Nn) cnt[i] = 0;
}

__global__ __launch_bounds__(256) void hist_dst(
    const int* __restrict__ ei, int* __restrict__ cnt, int E, int ET)
{
    int i = blockIdx.x * blockDim.x + threadIdx.x;
    if (i >= ET) return;
    int d = (i < E) ? ei[(size_t)E + i] : i - E;
    atomicAdd(&cnt[d], 1);
}

__global__ __launch_bounds__(1024) void scan1024(
    const int* __restrict__ cnt, int n, int* __restrict__ excl, int* __restrict__ bsum)
{
    __shared__ int sm[1024];
    int t = threadIdx.x;
    int gid = blockIdx.x * 1024 + t;
    int v = (gid < n) ? cnt[gid] : 0;
    sm[t] = v;
    __syncthreads();
#pragma unroll
    for (int off = 1; off < 1024; off <<= 1) {
        int u = (t >= off) ? sm[t - off] : 0;
        __syncthreads();
        sm[t] += u;
        __syncthreads();
    }
    if (gid < n) excl[gid] = sm[t] - v;
    if (t == 1023) bsum[blockIdx.x] = sm[1023];
}

__global__ void scan_bsum(int* __restrict__ bsum, int nb) {
    if (threadIdx.x == 0 && blockIdx.x == 0) {
        int acc = 0;
        for (int i = 0; i < nb; i++) { int t = bsum[i]; bsum[i] = acc; acc += t; }
    }
}

__global__ __launch_bounds__(256) void add_offsets(
    const int* __restrict__ excl, const int* __restrict__ bsum,
    int* __restrict__ rowptr, int* __restrict__ cursor, int Nn, int ET)
{
    int i = blockIdx.x * blockDim.x + threadIdx.x;
    if (i < Nn) {
        int v = excl[i] + bsum[i >> 10];
        rowptr[i] = v;
        cursor[i] = v;
    } else if (i == Nn) {
        rowptr[Nn] = ET;
    }
}

__global__ __launch_bounds__(256) void scatter_edges(
    const int* __restrict__ ei, int* __restrict__ cursor,
    int* __restrict__ srcidx, int E, int ET)
{
    int i = blockIdx.x * blockDim.x + threadIdx.x;
    if (i >= ET) return;
    int s, d;
    if (i < E) { s = ei[i]; d = ei[(size_t)E + i]; }
    else       { s = d = i - E; }
    int pos = atomicAdd(&cursor[d], 1);
    srcidx[pos] = s;
}

// ---------------------------------------------------------------------------
// Per-node alpha dots (one warp per node)
// ---------------------------------------------------------------------------
__global__ __launch_bounds__(256) void node_prep(
    const float* __restrict__ h, const float* __restrict__ a_s,
    const float* __restrict__ a_d,
    float* __restrict__ as_, float* __restrict__ ad_, int Nn, int F)
{
    int warp = (blockIdx.x * blockDim.x + threadIdx.x) >> 5;
    int lane = threadIdx.x & 31;
    if (warp >= Nn) return;
    const float* row = h + (size_t)warp * F;
    float s1 = 0.f, s2 = 0.f;
    for (int f = lane; f < F; f += 32) {
        float v = row[f];
        s1 = fmaf(v, a_s[f], s1);
        s2 = fmaf(v, a_d[f], s2);
    }
#pragma unroll
    for (int o = 16; o; o >>= 1) {
        s1 += __shfl_down_sync(0xffffffffu, s1, o);
        s2 += __shfl_down_sync(0xffffffffu, s2, o);
    }
    if (lane == 0) { as_[warp] = s1; ad_[warp] = s2; }
}

// ---------------------------------------------------------------------------
// Fused GAT aggregation over CSR: online softmax + weighted gather + bias(+relu)
// One warp per dst node. m uses a finite -BIG sentinel (NOT -inf).
// ---------------------------------------------------------------------------
template<int F, bool RELU>
__global__ __launch_bounds__(256) void gat_agg_csr(
    const int* __restrict__ rowptr, const int* __restrict__ srcidx,
    const float* __restrict__ as_, const float* __restrict__ ad_,
    const float* __restrict__ h, const float* __restrict__ bias,
    float* __restrict__ out, int Nn)
{
    constexpr int NV = F / 128;   // float4s per lane
    int warp = (blockIdx.x * blockDim.x + threadIdx.x) >> 5;
    int lane = threadIdx.x & 31;
    if (warp >= Nn) return;

    const int beg = rowptr[warp];
    const int end = rowptr[warp + 1];
    const float adv = ad_[warp];

    float m = NEG_BIG, s = 0.f;
    for (int i = beg + lane; i < end; i += 32) {
        float x = as_[srcidx[i]] + adv;
        x = fmaxf(x, 0.2f * x);
        float mn = fmaxf(m, x);
        s = s * __expf(m - mn) + __expf(x - mn);
        m = mn;
    }
#pragma unroll
    for (int o = 16; o; o >>= 1) {
        float mo = __shfl_xor_sync(0xffffffffu, m, o);
        float so = __shfl_xor_sync(0xffffffffu, s, o);
        float mn = fmaxf(m, mo);
        s = s * __expf(m - mn) + so * __expf(mo - mn);
        m = mn;
    }
    const float inv = 1.f / s;

    float4 acc[NV];
#pragma unroll
    for (int j = 0; j < NV; j++) acc[j] = make_float4(0.f, 0.f, 0.f, 0.f);

    for (int i = beg; i < end; i++) {
        int src = srcidx[i];
        float x = as_[src] + adv;
        x = fmaxf(x, 0.2f * x);
        float w = __expf(x - m);
        const float4* hp = (const float4*)(h + (size_t)src * F);
#pragma unroll
        for (int j = 0; j < NV; j++) {
            float4 v = hp[lane + 32 * j];
            acc[j].x = fmaf(w, v.x, acc[j].x);
            acc[j].y = fmaf(w, v.y, acc[j].y);
            acc[j].z = fmaf(w, v.z, acc[j].z);
            acc[j].w = fmaf(w, v.w, acc[j].w);
        }
    }

    float4* op = (float4*)(out + (size_t)warp * F);
    const float4* bp = (const float4*)bias;
#pragma unroll
    for (int j = 0; j < NV; j++) {
        float4 b = bp[lane + 32 * j];
        float4 r;
        r.x = fmaf(acc[j].x, inv, b.x);
        r.y = fmaf(acc[j].y, inv, b.y);
        r.z = fmaf(acc[j].z, inv, b.z);
        r.w = fmaf(acc[j].w, inv, b.w);
        if (RELU) {
            r.x = fmaxf(r.x, 0.f); r.y = fmaxf(r.y, 0.f);
            r.z = fmaxf(r.z, 0.f); r.w = fmaxf(r.w, 0.f);
        }
        op[lane + 32 * j] = r;
    }
}

// ---------------------------------------------------------------------------
// Layer 3: h3 = z2 @ W3 (K=256, N=2) + alpha dots. One warp per node.
// ---------------------------------------------------------------------------
__global__ __launch_bounds__(256) void layer3_prep(
    const float* __restrict__ z2, const float* __restrict__ W3,
    const float* __restrict__ a3s, const float* __restrict__ a3d,
    float* __restrict__ h3, float* __restrict__ as_, float* __restrict__ ad_,
    int Nn)
{
    int warp = (blockIdx.x * blockDim.x + threadIdx.x) >> 5;
    int lane = threadIdx.x & 31;
    if (warp >= Nn) return;
    const float* row = z2 + (size_t)warp * D2;
    float h0 = 0.f, h1 = 0.f;
    for (int f = lane; f < D2; f += 32) {
        float v = row[f];
        h0 = fmaf(v, W3[2 * f + 0], h0);
        h1 = fmaf(v, W3[2 * f + 1], h1);
    }
#pragma unroll
    for (int o = 16; o; o >>= 1) {
        h0 += __shfl_down_sync(0xffffffffu, h0, o);
        h1 += __shfl_down_sync(0xffffffffu, h1, o);
    }
    if (lane == 0) {
        h3[2 * warp + 0] = h0;
        h3[2 * warp + 1] = h1;
        as_[warp] = h0 * a3s[0] + h1 * a3s[1];
        ad_[warp] = h0 * a3d[0] + h1 * a3d[1];
    }
}

// ---------------------------------------------------------------------------
// Layer 3 aggregate (F=2) + bias + final softmax, fused. One warp per node.
// ---------------------------------------------------------------------------
__global__ __launch_bounds__(256) void gat_layer3_out(
    const int* __restrict__ rowptr, const int* __restrict__ srcidx,
    const float* __restrict__ as_, const float* __restrict__ ad_,
    const float* __restrict__ h3, const float* __restrict__ b3,
    float* __restrict__ out, int Nn)
{
    int warp = (blockIdx.x * blockDim.x + threadIdx.x) >> 5;
    int lane = threadIdx.x & 31;
    if (warp >= Nn) return;

    const int beg = rowptr[warp];
    const int end = rowptr[warp + 1];
    const float adv = ad_[warp];

    float m = NEG_BIG, s = 0.f;
    float a0 = 0.f, a1 = 0.f;
    for (int i = beg + lane; i < end; i += 32) {
        int src = srcidx[i];
        float x = as_[src] + adv;
        x = fmaxf(x, 0.2f * x);
        float mn = fmaxf(m, x);
        float sc = __expf(m - mn);
        float w  = __expf(x - mn);
        s  = s * sc + w;
        a0 = a0 * sc + w * h3[2 * src + 0];
        a1 = a1 * sc + w * h3[2 * src + 1];
        m = mn;
    }
#pragma unroll
    for (int o = 16; o; o >>= 1) {
        float mo  = __shfl_xor_sync(0xffffffffu, m, o);
        float so  = __shfl_xor_sync(0xffffffffu, s, o);
        float a0o = __shfl_xor_sync(0xffffffffu, a0, o);
        float a1o = __shfl_xor_sync(0xffffffffu, a1, o);
        float mn = fmaxf(m, mo);
        float c0 = __expf(m - mn), c1 = __expf(mo - mn);
        s  = s * c0 + so * c1;
        a0 = a0 * c0 + a0o * c1;
        a1 = a1 * c0 + a1o * c1;
        m = mn;
    }
    if (lane == 0) {
        float inv = 1.f / s;
        float v0 = a0 * inv + b3[0];
        float v1 = a1 * inv + b3[1];
        float mm = fmaxf(v0, v1);
        float e0 = __expf(v0 - mm), e1 = __expf(v1 - mm);
        float d = 1.f / (e0 + e1);
        out[2 * warp + 0] = e0 * d;
        out[2 * warp + 1] = e1 * d;
    }
}

// ---------------------------------------------------------------------------
// Launch
// ---------------------------------------------------------------------------
extern "C" void kernel_launch(void* const* d_in, const int* in_sizes, int n_in,
                              void* d_out, int out_size)
{
    const float* x  = (const float*)d_in[0];
    const int*   ei = (const int*)d_in[1];   // int32 (JAX x64 disabled)
    const float *W1 = (const float*)d_in[3],  *a1s = (const float*)d_in[4],
                *a1d = (const float*)d_in[5], *b1  = (const float*)d_in[6];
    const float *W2 = (const float*)d_in[7],  *a2s = (const float*)d_in[8],
                *a2d = (const float*)d_in[9], *b2  = (const float*)d_in[10];
    const float *W3 = (const float*)d_in[11], *a3s = (const float*)d_in[12],
                *a3d = (const float*)d_in[13], *b3 = (const float*)d_in[14];

    const int Nn = in_sizes[2];
    const int E  = in_sizes[1] / 2;
    const int ET = E + Nn;

    float *h, *agg, *as_, *ad_, *h3;
    int *cnt, *excl, *bsum, *rowptr, *cursor, *srcidx;
    cudaGetSymbolAddress((void**)&h,      g_h);
    cudaGetSymbolAddress((void**)&agg,    g_agg);
    cudaGetSymbolAddress((void**)&as_,    g_as);
    cudaGetSymbolAddress((void**)&ad_,    g_ad);
    cudaGetSymbolAddress((void**)&h3,     g_h3);
    cudaGetSymbolAddress((void**)&cnt,    g_cnt);
    cudaGetSymbolAddress((void**)&excl,   g_excl);
    cudaGetSymbolAddress((void**)&bsum,   g_bsum);
    cudaGetSymbolAddress((void**)&rowptr, g_rowptr);
    cudaGetSymbolAddress((void**)&cursor, g_cursor);
    cudaGetSymbolAddress((void**)&srcidx, g_srcidx);

    const int TB = 256;
    const int nodeWarpBlocks = (int)(((size_t)Nn * 32 + TB - 1) / TB);
    const int edgeBlocks     = (ET + TB - 1) / TB;
    const int nodeBlocks     = (Nn + TB) / TB;
    const int scanBlocks     = (Nn + 1023) / 1024;

    // ---- CSR build (once; shared by all 3 layers) ----
    zero_counts<<<(Nn + TB - 1) / TB, TB>>>(cnt, Nn);
    hist_dst<<<edgeBlocks, TB>>>(ei, cnt, E, ET);
    scan1024<<<scanBlocks, 1024>>>(cnt, Nn, excl, bsum);
    scan_bsum<<<1, 32>>>(bsum, scanBlocks);
    add_offsets<<<nodeBlocks, TB>>>(excl, bsum, rowptr, cursor, Nn, ET);
    scatter_edges<<<edgeBlocks, TB>>>(ei, cursor, srcidx, E, ET);

    // ---- Layer 1 (784 -> 128) ----
    {
        dim3 grid((Nn + 127) / 128, D1 / 128);
        gemm_tf32x2<<<grid, TB>>>(x, W1, h, Nn, D1, FIN);
    }
    node_prep<<<nodeWarpBlocks, TB>>>(h, a1s, a1d, as_, ad_, Nn, D1);
    gat_agg_csr<D1, true><<<nodeWarpBlocks, TB>>>(rowptr, srcidx, as_, ad_, h, b1, agg, Nn);

    // ---- Layer 2 (128 -> 256) ----
    {
        dim3 grid((Nn + 127) / 128, D2 / 128);
        gemm_tf32x2<<<grid, TB>>>(agg, W2, h, Nn, D2, D1);
    }
    node_prep<<<nodeWarpBlocks, TB>>>(h, a2s, a2d, as_, ad_, Nn, D2);
    gat_agg_csr<D2, true><<<nodeWarpBlocks, TB>>>(rowptr, srcidx, as_, ad_, h, b2, agg, Nn);

    // ---- Layer 3 (256 -> 2) + final softmax ----
    layer3_prep<<<nodeWarpBlocks, TB>>>(agg, W3, a3s, a3d, h3, as_, ad_, Nn);
    gat_layer3_out<<<nodeWarpBlocks, TB>>>(rowptr, srcidx, as_, ad_, h3, b3,
                                           (float*)d_out, Nn);
}

// round 8
// speedup vs baseline: 2.9712x; 1.0102x over previous
#include <cuda_runtime.h>
#include <math_constants.h>
#include <cstdint>

// ---------------------------------------------------------------------------
// Net_6906307412335: 3-layer GAT, N=100000, E=1600000 (+N self loops)
// F: 784 -> 128 -> 256 -> 2, edge-softmax attention, final softmax(axis=1)
// Round 8: cp.async double-buffered tf32x2 GEMM (raw fp32 smem, split at
// fragment load). Edge/agg path unchanged from passing round-7.
// ---------------------------------------------------------------------------

#define NN_MAX    100000
#define EE_MAX    1600000
#define ET_MAX    (EE_MAX + NN_MAX)
#define FIN       784
#define D1        128
#define D2        256
#define NEG_BIG   (-3.0e38f)

// Scratch (device globals: allocation-free rule)
__device__ float g_h   [(size_t)NN_MAX * 256];
__device__ float g_agg [(size_t)NN_MAX * 256];
__device__ float g_as  [NN_MAX];
__device__ float g_ad  [NN_MAX];
__device__ float g_h3  [2 * NN_MAX];
// CSR scratch
__device__ int   g_cnt   [NN_MAX];
__device__ int   g_excl  [NN_MAX];
__device__ int   g_bsum  [256];
__device__ int   g_rowptr[NN_MAX + 1];
__device__ int   g_cursor[NN_MAX + 1];
__device__ int   g_srcidx[ET_MAX];

// ---------------------------------------------------------------------------
// tf32x2 split + mma helpers
// ---------------------------------------------------------------------------
__device__ __forceinline__ void split_tf32(float v, uint32_t& hi, uint32_t& lo) {
    asm("cvt.rna.tf32.f32 %0, %1;" : "=r"(hi) : "f"(v));
    float h = __uint_as_float(hi);
    asm("cvt.rna.tf32.f32 %0, %1;" : "=r"(lo) : "f"(v - h));
}

__device__ __forceinline__ void mma_tf32(float* c, const uint32_t* a, const uint32_t* b) {
    asm volatile(
        "mma.sync.aligned.m16n8k8.row.col.f32.tf32.tf32.f32 "
        "{%0,%1,%2,%3}, {%4,%5,%6,%7}, {%8,%9}, {%0,%1,%2,%3};"
        : "+f"(c[0]), "+f"(c[1]), "+f"(c[2]), "+f"(c[3])
        : "r"(a[0]), "r"(a[1]), "r"(a[2]), "r"(a[3]), "r"(b[0]), "r"(b[1]));
}

__device__ __forceinline__ void cp16(uint32_t saddr, const void* gptr, int srcBytes) {
    asm volatile("cp.async.cg.shared.global [%0], [%1], 16, %2;\n"
                 :: "r"(saddr), "l"(gptr), "r"(srcBytes));
}

#define APITCH 20    // A smem row pitch in floats (16 data + 4 pad), 80B (16B-aligned)
#define BPITCH 136   // B smem row pitch in floats (128 data + 8 pad), 544B (16B-aligned)

// ---------------------------------------------------------------------------
// Pipelined tensor-core GEMM: C[M,N] = A[M,K] @ B[K,N], row-major.
// K % 16 == 0, N % 128 == 0. Block 128x128x16, 256 thr, warp tile 64x32.
// Double-buffered cp.async staging of RAW fp32; tf32 hi/lo split at frag load.
// 3 mma passes per tile: hi*hi + hi*lo + lo*hi (~fp32 accuracy).
// ---------------------------------------------------------------------------
__global__ __launch_bounds__(256) void gemm_tf32x2(
    const float* __restrict__ A, const float* __restrict__ B,
    float* __restrict__ C, int M, int N, int K)
{
    __shared__ float As[2][128 * APITCH];   // 2*10240B
    __shared__ float Bs[2][16 * BPITCH];    // 2*8704B

    const int tid  = threadIdx.x;
    const int row0 = blockIdx.x * 128;
    const int col0 = blockIdx.y * 128;
    const int lane = tid & 31;
    const int wid  = tid >> 5;
    const int wm   = (wid >> 2) * 64;
    const int wn   = (wid & 3) * 32;
    const int g    = lane >> 2;
    const int t4   = lane & 3;

    // staging coords (2 chunks of 16B each for A and B per thread)
    const int aRow0 = tid >> 2,  aK0 = (tid & 3) * 4;          // chunk 0
    const int aRow1 = (tid + 256) >> 2, aK1 = ((tid + 256) & 3) * 4;
    const int bRow0 = tid >> 5,  bN0 = (tid & 31) * 4;
    const int bRow1 = (tid + 256) >> 5, bN1 = ((tid + 256) & 31) * 4;

    const uint32_t sA = (uint32_t)__cvta_generic_to_shared(&As[0][0]);
    const uint32_t sB = (uint32_t)__cvta_generic_to_shared(&Bs[0][0]);
    const uint32_t bufA = 128 * APITCH * 4;   // bytes per A buffer
    const uint32_t bufB = 16 * BPITCH * 4;

    float acc[4][4][4];
#pragma unroll
    for (int mt = 0; mt < 4; mt++)
#pragma unroll
        for (int nt = 0; nt < 4; nt++)
#pragma unroll
            for (int r = 0; r < 4; r++) acc[mt][nt][r] = 0.f;

    const int nsteps = K >> 4;

    auto stage = [&](int buf, int k0) {
        // A: 128 rows x 16 floats
        {
            bool v0 = (row0 + aRow0) < M;
            const float* gp = A + (size_t)(v0 ? row0 + aRow0 : 0) * K + k0 + aK0;
            cp16(sA + buf * bufA + (aRow0 * APITCH + aK0) * 4, gp, v0 ? 16 : 0);
            bool v1 = (row0 + aRow1) < M;
            const float* gq = A + (size_t)(v1 ? row0 + aRow1 : 0) * K + k0 + aK1;
            cp16(sA + buf * bufA + (aRow1 * APITCH + aK1) * 4, gq, v1 ? 16 : 0);
        }
        // B: 16 rows x 128 floats (always in-bounds: K%16==0, N%128==0)
        cp16(sB + buf * bufB + (bRow0 * BPITCH + bN0) * 4,
             B + (size_t)(k0 + bRow0) * N + col0 + bN0, 16);
        cp16(sB + buf * bufB + (bRow1 * BPITCH + bN1) * 4,
             B + (size_t)(k0 + bRow1) * N + col0 + bN1, 16);
    };

    stage(0, 0);
    asm volatile("cp.async.commit_group;\n");

    for (int step = 0; step < nsteps; step++) {
        const int buf = step & 1;
        if (step + 1 < nsteps) stage(buf ^ 1, (step + 1) << 4);
        asm volatile("cp.async.commit_group;\n");
        asm volatile("cp.async.wait_group 1;\n");
        __syncthreads();

        const float* Ab = &As[buf][0];
        const float* Bb = &Bs[buf][0];
#pragma unroll
        for (int ks = 0; ks < 2; ks++) {
            const int kb = ks * 8;
            uint32_t bh[4][2], bl[4][2];
#pragma unroll
            for (int nt = 0; nt < 4; nt++) {
                int n = wn + nt * 8 + g;
                float r0 = Bb[(kb + t4) * BPITCH + n];
                float r1 = Bb[(kb + t4 + 4) * BPITCH + n];
                split_tf32(r0, bh[nt][0], bl[nt][0]);
                split_tf32(r1, bh[nt][1], bl[nt][1]);
            }
#pragma unroll
            for (int mt = 0; mt < 4; mt++) {
                int mr = wm + mt * 16 + g;
                uint32_t ah[4], al[4];
                float a0 = Ab[mr * APITCH + kb + t4];
                float a1 = Ab[(mr + 8) * APITCH + kb + t4];
                float a2 = Ab[mr * APITCH + kb + t4 + 4];
                float a3 = Ab[(mr + 8) * APITCH + kb + t4 + 4];
                split_tf32(a0, ah[0], al[0]);
                split_tf32(a1, ah[1], al[1]);
                split_tf32(a2, ah[2], al[2]);
                split_tf32(a3, ah[3], al[3]);
#pragma unroll
                for (int nt = 0; nt < 4; nt++) {
                    mma_tf32(acc[mt][nt], ah, bh[nt]);   // hi*hi
                    mma_tf32(acc[mt][nt], ah, bl[nt]);   // hi*lo
                    mma_tf32(acc[mt][nt], al, bh[nt]);   // lo*hi
                }
            }
        }
        __syncthreads();   // all reads of buf done before it is restaged
    }

    // ---- epilogue ----
#pragma unroll
    for (int mt = 0; mt < 4; mt++) {
#pragma unroll
        for (int nt = 0; nt < 4; nt++) {
            int r = row0 + wm + mt * 16 + g;
            int c = col0 + wn + nt * 8 + 2 * t4;
            if (r < M)
                *(float2*)(C + (size_t)r * N + c) =
                    make_float2(acc[mt][nt][0], acc[mt][nt][1]);
            if (r + 8 < M)
                *(float2*)(C + (size_t)(r + 8) * N + c) =
                    make_float2(acc[mt][nt][2], acc[mt][nt][3]);
        }
    }
}

// ---------------------------------------------------------------------------
// CSR construction (counting sort by dst)
// ---------------------------------------------------------------------------
__global__ __launch_bounds__(256) void zero_counts(int* __restrict__ cnt, int Nn) {
    int i = blockIdx.x * blockDim.x + threadIdx.x;
    if (i < Nn) cnt[i] = 0;
}

__global__ __launch_bounds__(256) void hist_dst(
    const int* __restrict__ ei, int* __restrict__ cnt, int E, int ET)
{
    int i = blockIdx.x * blockDim.x + threadIdx.x;
    if (i >= ET) return;
    int d = (i < E) ? ei[(size_t)E + i] : i - E;
    atomicAdd(&cnt[d], 1);
}

__global__ __launch_bounds__(1024) void scan1024(
    const int* __restrict__ cnt, int n, int* __restrict__ excl, int* __restrict__ bsum)
{
    __shared__ int sm[1024];
    int t = threadIdx.x;
    int gid = blockIdx.x * 1024 + t;
    int v = (gid < n) ? cnt[gid] : 0;
    sm[t] = v;
    __syncthreads();
#pragma unroll
    for (int off = 1; off < 1024; off <<= 1) {
        int u = (t >= off) ? sm[t - off] : 0;
        __syncthreads();
        sm[t] += u;
        __syncthreads();
    }
    if (gid < n) excl[gid] = sm[t] - v;
    if (t == 1023) bsum[blockIdx.x] = sm[1023];
}

__global__ void scan_bsum(int* __restrict__ bsum, int nb) {
    if (threadIdx.x == 0 && blockIdx.x == 0) {
        int acc = 0;
        for (int i = 0; i < nb; i++) { int t = bsum[i]; bsum[i] = acc; acc += t; }
    }
}

__global__ __launch_bounds__(256) void add_offsets(
    const int* __restrict__ excl, const int* __restrict__ bsum,
    int* __restrict__ rowptr, int* __restrict__ cursor, int Nn, int ET)
{
    int i = blockIdx.x * blockDim.x + threadIdx.x;
    if (i < Nn) {
        int v = excl[i] + bsum[i >> 10];
        rowptr[i] = v;
        cursor[i] = v;
    } else if (i == Nn) {
        rowptr[Nn] = ET;
    }
}

__global__ __launch_bounds__(256) void scatter_edges(
    const int* __restrict__ ei, int* __restrict__ cursor,
    int* __restrict__ srcidx, int E, int ET)
{
    int i = blockIdx.x * blockDim.x + threadIdx.x;
    if (i >= ET) return;
    int s, d;
    if (i < E) { s = ei[i]; d = ei[(size_t)E + i]; }
    else       { s = d = i - E; }
    int pos = atomicAdd(&cursor[d], 1);
    srcidx[pos] = s;
}

// ---------------------------------------------------------------------------
// Per-node alpha dots (one warp per node)
// ---------------------------------------------------------------------------
__global__ __launch_bounds__(256) void node_prep(
    const float* __restrict__ h, const float* __restrict__ a_s,
    const float* __restrict__ a_d,
    float* __restrict__ as_, float* __restrict__ ad_, int Nn, int F)
{
    int warp = (blockIdx.x * blockDim.x + threadIdx.x) >> 5;
    int lane = threadIdx.x & 31;
    if (warp >= Nn) return;
    const float* row = h + (size_t)warp * F;
    float s1 = 0.f, s2 = 0.f;
    for (int f = lane; f < F; f += 32) {
        float v = row[f];
        s1 = fmaf(v, a_s[f], s1);
        s2 = fmaf(v, a_d[f], s2);
    }
#pragma unroll
    for (int o = 16; o; o >>= 1) {
        s1 += __shfl_down_sync(0xffffffffu, s1, o);
        s2 += __shfl_down_sync(0xffffffffu, s2, o);
    }
    if (lane == 0) { as_[warp] = s1; ad_[warp] = s2; }
}

// ---------------------------------------------------------------------------
// Fused GAT aggregation over CSR: online softmax + weighted gather + bias(+relu)
// One warp per dst node. m uses a finite -BIG sentinel (NOT -inf).
// ---------------------------------------------------------------------------
template<int F, bool RELU>
__global__ __launch_bounds__(256) void gat_agg_csr(
    const int* __restrict__ rowptr, const int* __restrict__ srcidx,
    const float* __restrict__ as_, const float* __restrict__ ad_,
    const float* __restrict__ h, const float* __restrict__ bias,
    float* __restrict__ out, int Nn)
{
    constexpr int NV = F / 128;   // float4s per lane
    int warp = (blockIdx.x * blockDim.x + threadIdx.x) >> 5;
    int lane = threadIdx.x & 31;
    if (warp >= Nn) return;

    const int beg = rowptr[warp];
    const int end = rowptr[warp + 1];
    const float adv = ad_[warp];

    float m = NEG_BIG, s = 0.f;
    for (int i = beg + lane; i < end; i += 32) {
        float x = as_[srcidx[i]] + adv;
        x = fmaxf(x, 0.2f * x);
        float mn = fmaxf(m, x);
        s = s * __expf(m - mn) + __expf(x - mn);
        m = mn;
    }
#pragma unroll
    for (int o = 16; o; o >>= 1) {
        float mo = __shfl_xor_sync(0xffffffffu, m, o);
        float so = __shfl_xor_sync(0xffffffffu, s, o);
        float mn = fmaxf(m, mo);
        s = s * __expf(m - mn) + so * __expf(mo - mn);
        m = mn;
    }
    const float inv = 1.f / s;

    float4 acc[NV];
#pragma unroll
    for (int j = 0; j < NV; j++) acc[j] = make_float4(0.f, 0.f, 0.f, 0.f);

    for (int i = beg; i < end; i++) {
        int src = srcidx[i];
        float x = as_[src] + adv;
        x = fmaxf(x, 0.2f * x);
        float w = __expf(x - m);
        const float4* hp = (const float4*)(h + (size_t)src * F);
#pragma unroll
        for (int j = 0; j < NV; j++) {
            float4 v = hp[lane + 32 * j];
            acc[j].x = fmaf(w, v.x, acc[j].x);
            acc[j].y = fmaf(w, v.y, acc[j].y);
            acc[j].z = fmaf(w, v.z, acc[j].z);
            acc[j].w = fmaf(w, v.w, acc[j].w);
        }
    }

    float4* op = (float4*)(out + (size_t)warp * F);
    const float4* bp = (const float4*)bias;
#pragma unroll
    for (int j = 0; j < NV; j++) {
        float4 b = bp[lane + 32 * j];
        float4 r;
        r.x = fmaf(acc[j].x, inv, b.x);
        r.y = fmaf(acc[j].y, inv, b.y);
        r.z = fmaf(acc[j].z, inv, b.z);
        r.w = fmaf(acc[j].w, inv, b.w);
        if (RELU) {
            r.x = fmaxf(r.x, 0.f); r.y = fmaxf(r.y, 0.f);
            r.z = fmaxf(r.z, 0.f); r.w = fmaxf(r.w, 0.f);
        }
        op[lane + 32 * j] = r;
    }
}

// ---------------------------------------------------------------------------
// Layer 3: h3 = z2 @ W3 (K=256, N=2) + alpha dots. One warp per node.
// ---------------------------------------------------------------------------
__global__ __launch_bounds__(256) void layer3_prep(
    const float* __restrict__ z2, const float* __restrict__ W3,
    const float* __restrict__ a3s, const float* __restrict__ a3d,
    float* __restrict__ h3, float* __restrict__ as_, float* __restrict__ ad_,
    int Nn)
{
    int warp = (blockIdx.x * blockDim.x + threadIdx.x) >> 5;
    int lane = threadIdx.x & 31;
    if (warp >= Nn) return;
    const float* row = z2 + (size_t)warp * D2;
    float h0 = 0.f, h1 = 0.f;
    for (int f = lane; f < D2; f += 32) {
        float v = row[f];
        h0 = fmaf(v, W3[2 * f + 0], h0);
        h1 = fmaf(v, W3[2 * f + 1], h1);
    }
#pragma unroll
    for (int o = 16; o; o >>= 1) {
        h0 += __shfl_down_sync(0xffffffffu, h0, o);
        h1 += __shfl_down_sync(0xffffffffu, h1, o);
    }
    if (lane == 0) {
        h3[2 * warp + 0] = h0;
        h3[2 * warp + 1] = h1;
        as_[warp] = h0 * a3s[0] + h1 * a3s[1];
        ad_[warp] = h0 * a3d[0] + h1 * a3d[1];
    }
}

// ---------------------------------------------------------------------------
// Layer 3 aggregate (F=2) + bias + final softmax, fused. One warp per node.
// ---------------------------------------------------------------------------
__global__ __launch_bounds__(256) void gat_layer3_out(
    const int* __restrict__ rowptr, const int* __restrict__ srcidx,
    const float* __restrict__ as_, const float* __restrict__ ad_,
    const float* __restrict__ h3, const float* __restrict__ b3,
    float* __restrict__ out, int Nn)
{
    int warp = (blockIdx.x * blockDim.x + threadIdx.x) >> 5;
    int lane = threadIdx.x & 31;
    if (warp >= Nn) return;

    const int beg = rowptr[warp];
    const int end = rowptr[warp + 1];
    const float adv = ad_[warp];

    float m = NEG_BIG, s = 0.f;
    float a0 = 0.f, a1 = 0.f;
    for (int i = beg + lane; i < end; i += 32) {
        int src = srcidx[i];
        float x = as_[src] + adv;
        x = fmaxf(x, 0.2f * x);
        float mn = fmaxf(m, x);
        float sc = __expf(m - mn);
        float w  = __expf(x - mn);
        s  = s * sc + w;
        a0 = a0 * sc + w * h3[2 * src + 0];
        a1 = a1 * sc + w * h3[2 * src + 1];
        m = mn;
    }
#pragma unroll
    for (int o = 16; o; o >>= 1) {
        float mo  = __shfl_xor_sync(0xffffffffu, m, o);
        float so  = __shfl_xor_sync(0xffffffffu, s, o);
        float a0o = __shfl_xor_sync(0xffffffffu, a0, o);
        float a1o = __shfl_xor_sync(0xffffffffu, a1, o);
        float mn = fmaxf(m, mo);
        float c0 = __expf(m - mn), c1 = __expf(mo - mn);
        s  = s * c0 + so * c1;
        a0 = a0 * c0 + a0o * c1;
        a1 = a1 * c0 + a1o * c1;
        m = mn;
    }
    if (lane == 0) {
        float inv = 1.f / s;
        float v0 = a0 * inv + b3[0];
        float v1 = a1 * inv + b3[1];
        float mm = fmaxf(v0, v1);
        float e0 = __expf(v0 - mm), e1 = __expf(v1 - mm);
        float d = 1.f / (e0 + e1);
        out[2 * warp + 0] = e0 * d;
        out[2 * warp + 1] = e1 * d;
    }
}

// ---------------------------------------------------------------------------
// Launch
// ---------------------------------------------------------------------------
extern "C" void kernel_launch(void* const* d_in, const int* in_sizes, int n_in,
                              void* d_out, int out_size)
{
    const float* x  = (const float*)d_in[0];
    const int*   ei = (const int*)d_in[1];   // int32 (JAX x64 disabled)
    const float *W1 = (const float*)d_in[3],  *a1s = (const float*)d_in[4],
                *a1d = (const float*)d_in[5], *b1  = (const float*)d_in[6];
    const float *W2 = (const float*)d_in[7],  *a2s = (const float*)d_in[8],
                *a2d = (const float*)d_in[9], *b2  = (const float*)d_in[10];
    const float *W3 = (const float*)d_in[11], *a3s = (const float*)d_in[12],
                *a3d = (const float*)d_in[13], *b3 = (const float*)d_in[14];

    const int Nn = in_sizes[2];
    const int E  = in_sizes[1] / 2;
    const int ET = E + Nn;

    float *h, *agg, *as_, *ad_, *h3;
    int *cnt, *excl, *bsum, *rowptr, *cursor, *srcidx;
    cudaGetSymbolAddress((void**)&h,      g_h);
    cudaGetSymbolAddress((void**)&agg,    g_agg);
    cudaGetSymbolAddress((void**)&as_,    g_as);
    cudaGetSymbolAddress((void**)&ad_,    g_ad);
    cudaGetSymbolAddress((void**)&h3,     g_h3);
    cudaGetSymbolAddress((void**)&cnt,    g_cnt);
    cudaGetSymbolAddress((void**)&excl,   g_excl);
    cudaGetSymbolAddress((void**)&bsum,   g_bsum);
    cudaGetSymbolAddress((void**)&rowptr, g_rowptr);
    cudaGetSymbolAddress((void**)&cursor, g_cursor);
    cudaGetSymbolAddress((void**)&srcidx, g_srcidx);

    const int TB = 256;
    const int nodeWarpBlocks = (int)(((size_t)Nn * 32 + TB - 1) / TB);
    const int edgeBlocks     = (ET + TB - 1) / TB;
    const int nodeBlocks     = (Nn + TB) / TB;
    const int scanBlocks     = (Nn + 1023) / 1024;

    // ---- CSR build (once; shared by all 3 layers) ----
    zero_counts<<<(Nn + TB - 1) / TB, TB>>>(cnt, Nn);
    hist_dst<<<edgeBlocks, TB>>>(ei, cnt, E, ET);
    scan1024<<<scanBlocks, 1024>>>(cnt, Nn, excl, bsum);
    scan_bsum<<<1, 32>>>(bsum, scanBlocks);
    add_offsets<<<nodeBlocks, TB>>>(excl, bsum, rowptr, cursor, Nn, ET);
    scatter_edges<<<edgeBlocks, TB>>>(ei, cursor, srcidx, E, ET);

    // ---- Layer 1 (784 -> 128) ----
    {
        dim3 grid((Nn + 127) / 128, D1 / 128);
        gemm_tf32x2<<<grid, TB>>>(x, W1, h, Nn, D1, FIN);
    }
    node_prep<<<nodeWarpBlocks, TB>>>(h, a1s, a1d, as_, ad_, Nn, D1);
    gat_agg_csr<D1, true><<<nodeWarpBlocks, TB>>>(rowptr, srcidx, as_, ad_, h, b1, agg, Nn);

    // ---- Layer 2 (128 -> 256) ----
    {
        dim3 grid((Nn + 127) / 128, D2 / 128);
        gemm_tf32x2<<<grid, TB>>>(agg, W2, h, Nn, D2, D1);
    }
    node_prep<<<nodeWarpBlocks, TB>>>(h, a2s, a2d, as_, ad_, Nn, D2);
    gat_agg_csr<D2, true><<<nodeWarpBlocks, TB>>>(rowptr, srcidx, as_, ad_, h, b2, agg, Nn);

    // ---- Layer 3 (256 -> 2) + final softmax ----
    layer3_prep<<<nodeWarpBlocks, TB>>>(agg, W3, a3s, a3d, h3, as_, ad_, Nn);
    gat_layer3_out<<<nodeWarpBlocks, TB>>>(rowptr, srcidx, as_, ad_, h3, b3,
                                           (float*)d_out, Nn);
}

// round 9
// speedup vs baseline: 3.3449x; 1.1258x over previous
#include <cuda_runtime.h>
#include <cuda_bf16.h>
#include <math_constants.h>
#include <cstdint>

// ---------------------------------------------------------------------------
// Net_6906307412335: 3-layer GAT, N=100000, E=1600000 (+N self loops)
// F: 784 -> 128 -> 256 -> 2, edge-softmax attention, final softmax(axis=1)
// Round 9: GEMM inner math bf16x2 3-term (m16n8k16) -- half the mma
// instructions of the tf32 path. cp.async double-buffered raw-fp32 staging,
// split to bf16 hi/lo at fragment load. GEMM1 moved to launch slot 4 so the
// fixed ncu capture window lands on it.
// ---------------------------------------------------------------------------

#define NN_MAX    100000
#define EE_MAX    1600000
#define ET_MAX    (EE_MAX + NN_MAX)
#define FIN       784
#define D1        128
#define D2        256
#define NEG_BIG   (-3.0e38f)

// Scratch (device globals: allocation-free rule)
__device__ float g_h   [(size_t)NN_MAX * 256];
__device__ float g_agg [(size_t)NN_MAX * 256];
__device__ float g_as  [NN_MAX];
__device__ float g_ad  [NN_MAX];
__device__ float g_h3  [2 * NN_MAX];
// CSR scratch
__device__ int   g_cnt   [NN_MAX];
__device__ int   g_excl  [NN_MAX];
__device__ int   g_bsum  [256];
__device__ int   g_rowptr[NN_MAX + 1];
__device__ int   g_cursor[NN_MAX + 1];
__device__ int   g_srcidx[ET_MAX];

// ---------------------------------------------------------------------------
// bf16x2 split + mma helpers
// ---------------------------------------------------------------------------
__device__ __forceinline__ uint32_t pack_bf16(float x, float y) {
    __nv_bfloat162 t = __floats2bfloat162_rn(x, y);   // .x = low half
    return *reinterpret_cast<uint32_t*>(&t);
}

// v = hi + lo with hi,lo bf16-representable; returns packed pair regs.
__device__ __forceinline__ void split2_bf16(float x, float y,
                                            uint32_t& h, uint32_t& l) {
    __nv_bfloat16 hx = __float2bfloat16_rn(x);
    __nv_bfloat16 hy = __float2bfloat16_rn(y);
    float rx = x - __bfloat162float(hx);
    float ry = y - __bfloat162float(hy);
    __nv_bfloat162 hp; hp.x = hx; hp.y = hy;
    h = *reinterpret_cast<uint32_t*>(&hp);
    l = pack_bf16(rx, ry);
}

__device__ __forceinline__ void mma_bf16(float* c, const uint32_t* a, const uint32_t* b) {
    asm volatile(
        "mma.sync.aligned.m16n8k16.row.col.f32.bf16.bf16.f32 "
        "{%0,%1,%2,%3}, {%4,%5,%6,%7}, {%8,%9}, {%0,%1,%2,%3};"
        : "+f"(c[0]), "+f"(c[1]), "+f"(c[2]), "+f"(c[3])
        : "r"(a[0]), "r"(a[1]), "r"(a[2]), "r"(a[3]), "r"(b[0]), "r"(b[1]));
}

__device__ __forceinline__ void cp16(uint32_t saddr, const void* gptr, int srcBytes) {
    asm volatile("cp.async.cg.shared.global [%0], [%1], 16, %2;\n"
                 :: "r"(saddr), "l"(gptr), "r"(srcBytes));
}

#define APITCH 20    // A smem pitch in floats (16 data + 4 pad), 80B, 16B-aligned
#define BPITCH 132   // B smem pitch in floats (128 data + 4 pad), 528B, 16B-aligned
                     // 2*t4*BPITCH mod 32 banks = {0,8,16,24} -> conflict-free frags

// ---------------------------------------------------------------------------
// Pipelined tensor-core GEMM: C[M,N] = A[M,K] @ B[K,N], row-major.
// K % 16 == 0, N % 128 == 0. Block 128x128x16, 256 thr, warp tile 64x32.
// bf16 m16n8k16, 3 passes: hi*hi + hi*lo + lo*hi (rel err ~1e-5).
// ---------------------------------------------------------------------------
__global__ __launch_bounds__(256) void gemm_bf16x3(
    const float* __restrict__ A, const float* __restrict__ B,
    float* __restrict__ C, int M, int N, int K)
{
    __shared__ float As[2][128 * APITCH];
    __shared__ float Bs[2][16 * BPITCH];

    const int tid  = threadIdx.x;
    const int row0 = blockIdx.x * 128;
    const int col0 = blockIdx.y * 128;
    const int lane = tid & 31;
    const int wid  = tid >> 5;
    const int wm   = (wid >> 2) * 64;
    const int wn   = (wid & 3) * 32;
    const int g    = lane >> 2;
    const int t4   = lane & 3;

    const int aRow0 = tid >> 2,        aK0 = (tid & 3) * 4;
    const int aRow1 = (tid + 256) >> 2, aK1 = ((tid + 256) & 3) * 4;
    const int bRow0 = tid >> 5,        bN0 = (tid & 31) * 4;
    const int bRow1 = (tid + 256) >> 5, bN1 = ((tid + 256) & 31) * 4;

    const uint32_t sA = (uint32_t)__cvta_generic_to_shared(&As[0][0]);
    const uint32_t sB = (uint32_t)__cvta_generic_to_shared(&Bs[0][0]);
    const uint32_t bufA = 128 * APITCH * 4;
    const uint32_t bufB = 16 * BPITCH * 4;

    float acc[4][4][4];
#pragma unroll
    for (int mt = 0; mt < 4; mt++)
#pragma unroll
        for (int nt = 0; nt < 4; nt++)
#pragma unroll
            for (int r = 0; r < 4; r++) acc[mt][nt][r] = 0.f;

    const int nsteps = K >> 4;

    auto stage = [&](int buf, int k0) {
        bool v0 = (row0 + aRow0) < M;
        const float* gp = A + (size_t)(v0 ? row0 + aRow0 : 0) * K + k0 + aK0;
        cp16(sA + buf * bufA + (aRow0 * APITCH + aK0) * 4, gp, v0 ? 16 : 0);
        bool v1 = (row0 + aRow1) < M;
        const float* gq = A + (size_t)(v1 ? row0 + aRow1 : 0) * K + k0 + aK1;
        cp16(sA + buf * bufA + (aRow1 * APITCH + aK1) * 4, gq, v1 ? 16 : 0);
        cp16(sB + buf * bufB + (bRow0 * BPITCH + bN0) * 4,
             B + (size_t)(k0 + bRow0) * N + col0 + bN0, 16);
        cp16(sB + buf * bufB + (bRow1 * BPITCH + bN1) * 4,
             B + (size_t)(k0 + bRow1) * N + col0 + bN1, 16);
    };

    stage(0, 0);
    asm volatile("cp.async.commit_group;\n");

    for (int step = 0; step < nsteps; step++) {
        const int buf = step & 1;
        if (step + 1 < nsteps) stage(buf ^ 1, (step + 1) << 4);
        asm volatile("cp.async.commit_group;\n");
        asm volatile("cp.async.wait_group 1;\n");
        __syncthreads();

        const float* Ab = &As[buf][0];
        const float* Bb = &Bs[buf][0];

        // B fragments: b0 = {B[2t4][n], B[2t4+1][n]}, b1 = same at k+8
        uint32_t bh[4][2], bl[4][2];
#pragma unroll
        for (int nt = 0; nt < 4; nt++) {
            int n = wn + nt * 8 + g;
            float x0 = Bb[(2 * t4)     * BPITCH + n];
            float x1 = Bb[(2 * t4 + 1) * BPITCH + n];
            float x2 = Bb[(2 * t4 + 8) * BPITCH + n];
            float x3 = Bb[(2 * t4 + 9) * BPITCH + n];
            split2_bf16(x0, x1, bh[nt][0], bl[nt][0]);
            split2_bf16(x2, x3, bh[nt][1], bl[nt][1]);
        }
#pragma unroll
        for (int mt = 0; mt < 4; mt++) {
            int r = wm + mt * 16 + g;
            // a0={A[g][2t4..]}, a1=row+8, a2=k+8, a3=row+8,k+8
            float2 p0 = *(const float2*)&Ab[r       * APITCH + 2 * t4];
            float2 p1 = *(const float2*)&Ab[(r + 8) * APITCH + 2 * t4];
            float2 p2 = *(const float2*)&Ab[r       * APITCH + 2 * t4 + 8];
            float2 p3 = *(const float2*)&Ab[(r + 8) * APITCH + 2 * t4 + 8];
            uint32_t ah[4], al[4];
            split2_bf16(p0.x, p0.y, ah[0], al[0]);
            split2_bf16(p1.x, p1.y, ah[1], al[1]);
            split2_bf16(p2.x, p2.y, ah[2], al[2]);
            split2_bf16(p3.x, p3.y, ah[3], al[3]);
#pragma unroll
            for (int nt = 0; nt < 4; nt++) {
                mma_bf16(acc[mt][nt], ah, bh[nt]);   // hi*hi
                mma_bf16(acc[mt][nt], ah, bl[nt]);   // hi*lo
                mma_bf16(acc[mt][nt], al, bh[nt]);   // lo*hi
            }
        }
        __syncthreads();
    }

    // ---- epilogue (C frag layout: c0,c1 row g; c2,c3 row g+8) ----
#pragma unroll
    for (int mt = 0; mt < 4; mt++) {
#pragma unroll
        for (int nt = 0; nt < 4; nt++) {
            int r = row0 + wm + mt * 16 + g;
            int c = col0 + wn + nt * 8 + 2 * t4;
            if (r < M)
                *(float2*)(C + (size_t)r * N + c) =
                    make_float2(acc[mt][nt][0], acc[mt][nt][1]);
            if (r + 8 < M)
                *(float2*)(C + (size_t)(r + 8) * N + c) =
                    make_float2(acc[mt][nt][2], acc[mt][nt][3]);
        }
    }
}

// ---------------------------------------------------------------------------
// CSR construction (counting sort by dst)
// ---------------------------------------------------------------------------
__global__ __launch_bounds__(256) void zero_counts(int* __restrict__ cnt, int Nn) {
    int i = blockIdx.x * blockDim.x + threadIdx.x;
    if (i < Nn) cnt[i] = 0;
}

__global__ __launch_bounds__(256) void hist_dst(
    const int* __restrict__ ei, int* __restrict__ cnt, int E, int ET)
{
    int i = blockIdx.x * blockDim.x + threadIdx.x;
    if (i >= ET) return;
    int d = (i < E) ? ei[(size_t)E + i] : i - E;
    atomicAdd(&cnt[d], 1);
}

__global__ __launch_bounds__(1024) void scan1024(
    const int* __restrict__ cnt, int n, int* __restrict__ excl, int* __restrict__ bsum)
{
    __shared__ int sm[1024];
    int t = threadIdx.x;
    int gid = blockIdx.x * 1024 + t;
    int v = (gid < n) ? cnt[gid] : 0;
    sm[t] = v;
    __syncthreads();
#pragma unroll
    for (int off = 1; off < 1024; off <<= 1) {
        int u = (t >= off) ? sm[t - off] : 0;
        __syncthreads();
        sm[t] += u;
        __syncthreads();
    }
    if (gid < n) excl[gid] = sm[t] - v;
    if (t == 1023) bsum[blockIdx.x] = sm[1023];
}

__global__ void scan_bsum(int* __restrict__ bsum, int nb) {
    if (threadIdx.x == 0 && blockIdx.x == 0) {
        int acc = 0;
        for (int i = 0; i < nb; i++) { int t = bsum[i]; bsum[i] = acc; acc += t; }
    }
}

__global__ __launch_bounds__(256) void add_offsets(
    const int* __restrict__ excl, const int* __restrict__ bsum,
    int* __restrict__ rowptr, int* __restrict__ cursor, int Nn, int ET)
{
    int i = blockIdx.x * blockDim.x + threadIdx.x;
    if (i < Nn) {
        int v = excl[i] + bsum[i >> 10];
        rowptr[i] = v;
        cursor[i] = v;
    } else if (i == Nn) {
        rowptr[Nn] = ET;
    }
}

__global__ __launch_bounds__(256) void scatter_edges(
    const int* __restrict__ ei, int* __restrict__ cursor,
    int* __restrict__ srcidx, int E, int ET)
{
    int i = blockIdx.x * blockDim.x + threadIdx.x;
    if (i >= ET) return;
    int s, d;
    if (i < E) { s = ei[i]; d = ei[(size_t)E + i]; }
    else       { s = d = i - E; }
    int pos = atomicAdd(&cursor[d], 1);
    srcidx[pos] = s;
}

// ---------------------------------------------------------------------------
// Per-node alpha dots (one warp per node)
// ---------------------------------------------------------------------------
__global__ __launch_bounds__(256) void node_prep(
    const float* __restrict__ h, const float* __restrict__ a_s,
    const float* __restrict__ a_d,
    float* __restrict__ as_, float* __restrict__ ad_, int Nn, int F)
{
    int warp = (blockIdx.x * blockDim.x + threadIdx.x) >> 5;
    int lane = threadIdx.x & 31;
    if (warp >= Nn) return;
    const float* row = h + (size_t)warp * F;
    float s1 = 0.f, s2 = 0.f;
    for (int f = lane; f < F; f += 32) {
        float v = row[f];
        s1 = fmaf(v, a_s[f], s1);
        s2 = fmaf(v, a_d[f], s2);
    }
#pragma unroll
    for (int o = 16; o; o >>= 1) {
        s1 += __shfl_down_sync(0xffffffffu, s1, o);
        s2 += __shfl_down_sync(0xffffffffu, s2, o);
    }
    if (lane == 0) { as_[warp] = s1; ad_[warp] = s2; }
}

// ---------------------------------------------------------------------------
// Fused GAT aggregation over CSR: online softmax + weighted gather + bias(+relu)
// One warp per dst node. m uses a finite -BIG sentinel (NOT -inf).
// ---------------------------------------------------------------------------
template<int F, bool RELU>
__global__ __launch_bounds__(256) void gat_agg_csr(
    const int* __restrict__ rowptr, const int* __restrict__ srcidx,
    const float* __restrict__ as_, const float* __restrict__ ad_,
    const float* __restrict__ h, const float* __restrict__ bias,
    float* __restrict__ out, int Nn)
{
    constexpr int NV = F / 128;   // float4s per lane
    int warp = (blockIdx.x * blockDim.x + threadIdx.x) >> 5;
    int lane = threadIdx.x & 31;
    if (warp >= Nn) return;

    const int beg = rowptr[warp];
    const int end = rowptr[warp + 1];
    const float adv = ad_[warp];

    float m = NEG_BIG, s = 0.f;
    for (int i = beg + lane; i < end; i += 32) {
        float x = as_[srcidx[i]] + adv;
        x = fmaxf(x, 0.2f * x);
        float mn = fmaxf(m, x);
        s = s * __expf(m - mn) + __expf(x - mn);
        m = mn;
    }
#pragma unroll
    for (int o = 16; o; o >>= 1) {
        float mo = __shfl_xor_sync(0xffffffffu, m, o);
        float so = __shfl_xor_sync(0xffffffffu, s, o);
        float mn = fmaxf(m, mo);
        s = s * __expf(m - mn) + so * __expf(mo - mn);
        m = mn;
    }
    const float inv = 1.f / s;

    float4 acc[NV];
#pragma unroll
    for (int j = 0; j < NV; j++) acc[j] = make_float4(0.f, 0.f, 0.f, 0.f);

    for (int i = beg; i < end; i++) {
        int src = srcidx[i];
        float x = as_[src] + adv;
        x = fmaxf(x, 0.2f * x);
        float w = __expf(x - m);
        const float4* hp = (const float4*)(h + (size_t)src * F);
#pragma unroll
        for (int j = 0; j < NV; j++) {
            float4 v = hp[lane + 32 * j];
            acc[j].x = fmaf(w, v.x, acc[j].x);
            acc[j].y = fmaf(w, v.y, acc[j].y);
            acc[j].z = fmaf(w, v.z, acc[j].z);
            acc[j].w = fmaf(w, v.w, acc[j].w);
        }
    }

    float4* op = (float4*)(out + (size_t)warp * F);
    const float4* bp = (const float4*)bias;
#pragma unroll
    for (int j = 0; j < NV; j++) {
        float4 b = bp[lane + 32 * j];
        float4 r;
        r.x = fmaf(acc[j].x, inv, b.x);
        r.y = fmaf(acc[j].y, inv, b.y);
        r.z = fmaf(acc[j].z, inv, b.z);
        r.w = fmaf(acc[j].w, inv, b.w);
        if (RELU) {
            r.x = fmaxf(r.x, 0.f); r.y = fmaxf(r.y, 0.f);
            r.z = fmaxf(r.z, 0.f); r.w = fmaxf(r.w, 0.f);
        }
        op[lane + 32 * j] = r;
    }
}

// ---------------------------------------------------------------------------
// Layer 3: h3 = z2 @ W3 (K=256, N=2) + alpha dots. One warp per node.
// ---------------------------------------------------------------------------
__global__ __launch_bounds__(256) void layer3_prep(
    const float* __restrict__ z2, const float* __restrict__ W3,
    const float* __restrict__ a3s, const float* __restrict__ a3d,
    float* __restrict__ h3, float* __restrict__ as_, float* __restrict__ ad_,
    int Nn)
{
    int warp = (blockIdx.x * blockDim.x + threadIdx.x) >> 5;
    int lane = threadIdx.x & 31;
    if (warp >= Nn) return;
    const float* row = z2 + (size_t)warp * D2;
    float h0 = 0.f, h1 = 0.f;
    for (int f = lane; f < D2; f += 32) {
        float v = row[f];
        h0 = fmaf(v, W3[2 * f + 0], h0);
        h1 = fmaf(v, W3[2 * f + 1], h1);
    }
#pragma unroll
    for (int o = 16; o; o >>= 1) {
        h0 += __shfl_down_sync(0xffffffffu, h0, o);
        h1 += __shfl_down_sync(0xffffffffu, h1, o);
    }
    if (lane == 0) {
        h3[2 * warp + 0] = h0;
        h3[2 * warp + 1] = h1;
        as_[warp] = h0 * a3s[0] + h1 * a3s[1];
        ad_[warp] = h0 * a3d[0] + h1 * a3d[1];
    }
}

// ---------------------------------------------------------------------------
// Layer 3 aggregate (F=2) + bias + final softmax, fused. One warp per node.
// ---------------------------------------------------------------------------
__global__ __launch_bounds__(256) void gat_layer3_out(
    const int* __restrict__ rowptr, const int* __restrict__ srcidx,
    const float* __restrict__ as_, const float* __restrict__ ad_,
    const float* __restrict__ h3, const float* __restrict__ b3,
    float* __restrict__ out, int Nn)
{
    int warp = (blockIdx.x * blockDim.x + threadIdx.x) >> 5;
    int lane = threadIdx.x & 31;
    if (warp >= Nn) return;

    const int beg = rowptr[warp];
    const int end = rowptr[warp + 1];
    const float adv = ad_[warp];

    float m = NEG_BIG, s = 0.f;
    float a0 = 0.f, a1 = 0.f;
    for (int i = beg + lane; i < end; i += 32) {
        int src = srcidx[i];
        float x = as_[src] + adv;
        x = fmaxf(x, 0.2f * x);
        float mn = fmaxf(m, x);
        float sc = __expf(m - mn);
        float w  = __expf(x - mn);
        s  = s * sc + w;
        a0 = a0 * sc + w * h3[2 * src + 0];
        a1 = a1 * sc + w * h3[2 * src + 1];
        m = mn;
    }
#pragma unroll
    for (int o = 16; o; o >>= 1) {
        float mo  = __shfl_xor_sync(0xffffffffu, m, o);
        float so  = __shfl_xor_sync(0xffffffffu, s, o);
        float a0o = __shfl_xor_sync(0xffffffffu, a0, o);
        float a1o = __shfl_xor_sync(0xffffffffu, a1, o);
        float mn = fmaxf(m, mo);
        float c0 = __expf(m - mn), c1 = __expf(mo - mn);
        s  = s * c0 + so * c1;
        a0 = a0 * c0 + a0o * c1;
        a1 = a1 * c0 + a1o * c1;
        m = mn;
    }
    if (lane == 0) {
        float inv = 1.f / s;
        float v0 = a0 * inv + b3[0];
        float v1 = a1 * inv + b3[1];
        float mm = fmaxf(v0, v1);
        float e0 = __expf(v0 - mm), e1 = __expf(v1 - mm);
        float d = 1.f / (e0 + e1);
        out[2 * warp + 0] = e0 * d;
        out[2 * warp + 1] = e1 * d;
    }
}

// ---------------------------------------------------------------------------
// Launch
// ---------------------------------------------------------------------------
extern "C" void kernel_launch(void* const* d_in, const int* in_sizes, int n_in,
                              void* d_out, int out_size)
{
    const float* x  = (const float*)d_in[0];
    const int*   ei = (const int*)d_in[1];   // int32 (JAX x64 disabled)
    const float *W1 = (const float*)d_in[3],  *a1s = (const float*)d_in[4],
                *a1d = (const float*)d_in[5], *b1  = (const float*)d_in[6];
    const float *W2 = (const float*)d_in[7],  *a2s = (const float*)d_in[8],
                *a2d = (const float*)d_in[9], *b2  = (const float*)d_in[10];
    const float *W3 = (const float*)d_in[11], *a3s = (const float*)d_in[12],
                *a3d = (const float*)d_in[13], *b3 = (const float*)d_in[14];

    const int Nn = in_sizes[2];
    const int E  = in_sizes[1] / 2;
    const int ET = E + Nn;

    float *h, *agg, *as_, *ad_, *h3;
    int *cnt, *excl, *bsum, *rowptr, *cursor, *srcidx;
    cudaGetSymbolAddress((void**)&h,      g_h);
    cudaGetSymbolAddress((void**)&agg,    g_agg);
    cudaGetSymbolAddress((void**)&as_,    g_as);
    cudaGetSymbolAddress((void**)&ad_,    g_ad);
    cudaGetSymbolAddress((void**)&h3,     g_h3);
    cudaGetSymbolAddress((void**)&cnt,    g_cnt);
    cudaGetSymbolAddress((void**)&excl,   g_excl);
    cudaGetSymbolAddress((void**)&bsum,   g_bsum);
    cudaGetSymbolAddress((void**)&rowptr, g_rowptr);
    cudaGetSymbolAddress((void**)&cursor, g_cursor);
    cudaGetSymbolAddress((void**)&srcidx, g_srcidx);

    const int TB = 256;
    const int nodeWarpBlocks = (int)(((size_t)Nn * 32 + TB - 1) / TB);
    const int edgeBlocks     = (ET + TB - 1) / TB;
    const int nodeBlocks     = (Nn + TB) / TB;
    const int scanBlocks     = (Nn + 1023) / 1024;

    // ---- CSR build interleaved with GEMM1 (GEMM1 at launch slot 4: the
    //      fixed ncu capture window profiles the 4th kernel launch) ----
    zero_counts<<<(Nn + TB - 1) / TB, TB>>>(cnt, Nn);                    // 1
    hist_dst<<<edgeBlocks, TB>>>(ei, cnt, E, ET);                        // 2
    scan1024<<<scanBlocks, 1024>>>(cnt, Nn, excl, bsum);                 // 3
    {
        dim3 grid((Nn + 127) / 128, D1 / 128);
        gemm_bf16x3<<<grid, TB>>>(x, W1, h, Nn, D1, FIN);                // 4 (profiled)
    }
    scan_bsum<<<1, 32>>>(bsum, scanBlocks);                              // 5
    add_offsets<<<nodeBlocks, TB>>>(excl, bsum, rowptr, cursor, Nn, ET); // 6
    scatter_edges<<<edgeBlocks, TB>>>(ei, cursor, srcidx, E, ET);        // 7

    // ---- Layer 1 (784 -> 128) ----
    node_prep<<<nodeWarpBlocks, TB>>>(h, a1s, a1d, as_, ad_, Nn, D1);
    gat_agg_csr<D1, true><<<nodeWarpBlocks, TB>>>(rowptr, srcidx, as_, ad_, h, b1, agg, Nn);

    // ---- Layer 2 (128 -> 256) ----
    {
        dim3 grid((Nn + 127) / 128, D2 / 128);
        gemm_bf16x3<<<grid, TB>>>(agg, W2, h, Nn, D2, D1);
    }
    node_prep<<<nodeWarpBlocks, TB>>>(h, a2s, a2d, as_, ad_, Nn, D2);
    gat_agg_csr<D2, true><<<nodeWarpBlocks, TB>>>(rowptr, srcidx, as_, ad_, h, b2, agg, Nn);

    // ---- Layer 3 (256 -> 2) + final softmax ----
    layer3_prep<<<nodeWarpBlocks, TB>>>(agg, W3, a3s, a3d, h3, as_, ad_, Nn);
    gat_layer3_out<<<nodeWarpBlocks, TB>>>(rowptr, srcidx, as_, ad_, h3, b3,
                                           (float*)d_out, Nn);
}